// round 10
// baseline (speedup 1.0000x reference)
#include <cuda_runtime.h>
#include <cuda_fp16.h>
#include <math.h>
#include <stdint.h>

#define BB 8
#define C 64
#define COUT 128
#define H 128
#define W 128
#define HW (H*W)
#define KC 64
#define NCHUNK 9
#define SK 72              // A smem k-stride (fp16): 144B rows, conflict-free ldmatrix
#define SKB 136            // B smem px-stride (fp16): 272B rows, conflict-free trans ldmatrix
#define EPSV 1e-5f

// ---------------- smem layouts (byte offsets) ----------------
// conv1 / deform:
#define OFF_A   0                       // 128*72*2  = 18432
#define OFF_B   18432                   // 64*136*2  = 17408
#define OFF_STG 35840                   // conv1: float [8][3][132] = 12672
#define SMEM_C1 (35840 + 12672)         // 48512
#define OFF_TAP 35840                   // deform: float2 [36][128] = 36864
#define SMEM_DEF (35840 + 36864)        // 72704
// conv2 (GEMM-ized):
#define C2_OFF_A   0                    // 32*72*2 = 4608
#define C2_OFF_B   4608                 // 64*136*2 = 17408
#define C2_OFF_STG 22016                // float [8][3][132] = 12672
#define SMEM_C2    34688

// ---------------- device scratch ----------------
__device__ float g_t[BB*2*C*HW];
__device__ float g_offs[BB*18*HW];
__device__ float g_modu[BB*9*HW];
__device__ float g_scale[2*C];
__device__ float g_shift[2*C];
__device__ __align__(16) unsigned short g_w1[NCHUNK*COUT*SK];
__device__ __align__(16) unsigned short g_w4[NCHUNK*COUT*SK];
__device__ __align__(16) unsigned short g_w2[18*32*SK];   // conv2 block-diag A

// ---------------- helpers ----------------
__device__ __forceinline__ uint32_t smem_u32(const void* p) {
    uint32_t a;
    asm("{ .reg .u64 t; cvta.to.shared.u64 t, %1; cvt.u32.u64 %0, t; }" : "=r"(a) : "l"(p));
    return a;
}
__device__ __forceinline__ unsigned short h_bits(float v) {
    __half h = __float2half_rn(v);
    return *reinterpret_cast<unsigned short*>(&h);
}
__device__ __forceinline__ void ldsm_x4(uint32_t a[4], uint32_t addr) {
    asm volatile("ldmatrix.sync.aligned.m8n8.x4.shared.b16 {%0,%1,%2,%3}, [%4];"
        : "=r"(a[0]), "=r"(a[1]), "=r"(a[2]), "=r"(a[3]) : "r"(addr));
}
__device__ __forceinline__ void ldsm_x2_t(uint32_t b[2], uint32_t addr) {
    asm volatile("ldmatrix.sync.aligned.m8n8.x2.trans.shared.b16 {%0,%1}, [%2];"
        : "=r"(b[0]), "=r"(b[1]) : "r"(addr));
}
__device__ __forceinline__ void mma_f16(float d[4], const uint32_t a[4], const uint32_t b[2]) {
    asm volatile("mma.sync.aligned.m16n8k16.row.col.f32.f16.f16.f32 "
        "{%0,%1,%2,%3}, {%4,%5,%6,%7}, {%8,%9}, {%0,%1,%2,%3};"
        : "+f"(d[0]), "+f"(d[1]), "+f"(d[2]), "+f"(d[3])
        : "r"(a[0]), "r"(a[1]), "r"(a[2]), "r"(a[3]), "r"(b[0]), "r"(b[1]));
}
__device__ __forceinline__ uint32_t a_addr(uint32_t base, int row0, int k0, int lane) {
    int q = lane >> 3;
    int row = row0 + (lane & 7) + (q & 1) * 8;
    int col = k0 + (q >> 1) * 8;
    return base + (uint32_t)(row * SK + col) * 2u;
}
__device__ __forceinline__ uint32_t b_addr_t(uint32_t base, int k0, int n0, int lane) {
    int row = k0 + (lane & 15);
    return base + (uint32_t)(row * SKB + n0) * 2u;
}
__device__ __forceinline__ float silu_f(float v) {
    return __fdividef(v, 1.f + __expf(-v));
}

// ---------------- weight prep ----------------
__global__ void prep_weights(const float* __restrict__ off_w1,
                             const float* __restrict__ mod_w1,
                             const float* __restrict__ wmain) {
    int i = blockIdx.x * 256 + threadIdx.x;
    if (i >= NCHUNK*COUT*KC) return;
    int ck = i / (COUT*KC);
    int r  = i - ck*(COUT*KC);
    int co = r >> 6;
    int j  = r & 63;
    int k = ck*KC + j;
    int c = k / 9, t = k - c*9;
    size_t soff = (size_t)(ck*COUT + co)*SK + j;
    float w1 = (co < 64) ? off_w1[(co*C + c)*9 + t] : mod_w1[((co-64)*C + c)*9 + t];
    g_w1[soff] = h_bits(w1);
    g_w4[soff] = h_bits(wmain[(co*C + c)*9 + t]);
}

__global__ void prep_w2(const float* __restrict__ off_w2,
                        const float* __restrict__ mod_w2) {
    int i = blockIdx.x * 256 + threadIdx.x;
    if (i >= 18*32*KC) return;
    int ck = i / (32*KC);
    int r  = i - ck*(32*KC);
    int row = r >> 6;
    int j   = r & 63;
    int kb = (ck % 9)*KC + j;
    int c = kb / 9, t = kb - c*9;
    int branch = ck / 9;
    float w = 0.f;
    if (branch == 0 && row < 18)       w = off_w2[(row*C + c)*9 + t];
    else if (branch == 1 && row >= 18 && row < 27) w = mod_w2[((row-18)*C + c)*9 + t];
    g_w2[(size_t)(ck*32 + row)*SK + j] = h_bits(w);
}

extern __shared__ char smem_dyn[];

// ---------------- shared GEMM consumer (M=128 variant) ----------------
__device__ __forceinline__ void mma_chunk(uint32_t smem_base, int lane, int wco, int wpx,
                                          float acc[2][8][4]) {
    uint32_t baseA = smem_base + OFF_A;
    uint32_t baseB = smem_base + OFF_B;
    #pragma unroll
    for (int ks = 0; ks < 4; ks++) {
        int k0 = ks * 16;
        uint32_t a[2][4];
        #pragma unroll
        for (int mt = 0; mt < 2; mt++)
            ldsm_x4(a[mt], a_addr(baseA, wco + mt*16, k0, lane));
        #pragma unroll
        for (int nt = 0; nt < 8; nt++) {
            uint32_t bh[2];
            ldsm_x2_t(bh, b_addr_t(baseB, k0, wpx + nt*8, lane));
            #pragma unroll
            for (int mt = 0; mt < 2; mt++)
                mma_f16(acc[mt][nt], a[mt], bh);
        }
    }
}

// ---------------- conv1: mma GEMM, smem-staged im2col producer --------------
__global__ __launch_bounds__(256) void conv1_t(const float* __restrict__ x,
                                               const float* __restrict__ b_off,
                                               const float* __restrict__ b_mod) {
    char* smem_c = smem_dyn;
    uint32_t smem_base = smem_u32(smem_c);
    int tid = threadIdx.x, wid = tid >> 5, lane = tid & 31;
    int blk = blockIdx.x;
    int b = blk >> 7, h = blk & 127;
    const float* xb = x + (size_t)b * C * HW;
    float* stg = (float*)(smem_c + OFF_STG);

    int wco = (wid >> 1) * 32;
    int wpx = (wid & 1) * 64;
    float acc[2][8][4];
    #pragma unroll
    for (int mt = 0; mt < 2; mt++)
        #pragma unroll
        for (int nt = 0; nt < 8; nt++)
            #pragma unroll
            for (int q = 0; q < 4; q++) acc[mt][nt][q] = 0.f;

    int px = tid & 127, kh = tid >> 7;
    if (tid < 48) stg[(tid >> 1)*132 + ((tid & 1) ? 129 : 0)] = 0.f;

    for (int ck = 0; ck < NCHUNK; ck++) {
        if (ck) __syncthreads();
        {
            const uint4* sa = (const uint4*)(g_w1 + (size_t)ck*COUT*SK);
            uint4* da = (uint4*)(smem_c + OFF_A);
            for (int i = tid; i < COUT*SK/8; i += 256) da[i] = sa[i];
        }
        int c_lo = (ck*KC) / 9;
        #pragma unroll
        for (int it = 0; it < 12; it++) {
            int i = it*256 + tid;
            int ch = i / 384;
            int rr = (i - ch*384) >> 7;
            int col = i & 127;
            int hh = h + rr - 1;
            float v = ((unsigned)hh < H) ? __ldg(xb + (size_t)(c_lo + ch)*HW + hh*W + col) : 0.f;
            stg[(ch*3 + rr)*132 + 1 + col] = v;
        }
        __syncthreads();
        {
            int k0h = ck*KC + kh*32;
            int c = k0h / 9, t = k0h - 9*c;
            #pragma unroll 8
            for (int kk2 = 0; kk2 < 32; kk2++) {
                int dy = t / 3, dxm = t - dy*3;
                float v = stg[((c - c_lo)*3 + dy)*132 + px + dxm];
                *(unsigned short*)(smem_c + OFF_B + (kh*32 + kk2)*(SKB*2) + px*2) = h_bits(v);
                if (++t == 9) { t = 0; c++; }
            }
        }
        __syncthreads();
        mma_chunk(smem_base, lane, wco, wpx, acc);
    }

    int g = lane >> 2, tg = lane & 3;
    float* dst = g_t + (size_t)b*COUT*HW + (size_t)h*W;
    #pragma unroll
    for (int mt = 0; mt < 2; mt++) {
        int co0 = wco + mt*16 + g;
        int co1 = co0 + 8;
        float bv0 = (co0 < 64) ? __ldg(b_off + co0) : __ldg(b_mod + co0 - 64);
        float bv1 = (co1 < 64) ? __ldg(b_off + co1) : __ldg(b_mod + co1 - 64);
        #pragma unroll
        for (int nt = 0; nt < 8; nt++) {
            int p2 = wpx + nt*8 + 2*tg;
            *(float2*)(dst + (size_t)co0*HW + p2) = make_float2(acc[mt][nt][0]+bv0, acc[mt][nt][1]+bv0);
            *(float2*)(dst + (size_t)co1*HW + p2) = make_float2(acc[mt][nt][2]+bv1, acc[mt][nt][3]+bv1);
        }
    }
}

// ---------------- BN stats ----------------
__inline__ __device__ float warpsum(float v) {
    #pragma unroll
    for (int o = 16; o; o >>= 1) v += __shfl_down_sync(0xFFFFFFFFu, v, o);
    return v;
}

__global__ __launch_bounds__(256) void bn_stats(const float* __restrict__ gam_off,
                                                const float* __restrict__ bet_off,
                                                const float* __restrict__ gam_mod,
                                                const float* __restrict__ bet_mod) {
    int ch = blockIdx.x;
    int tid = threadIdx.x;
    float s = 0.f, s2 = 0.f;
    for (int b = 0; b < BB; b++) {
        const float4* p = (const float4*)(g_t + ((size_t)(b*2*C + ch))*HW);
        for (int i = tid; i < HW/4; i += 256) {
            float4 v = p[i];
            s  += v.x + v.y + v.z + v.w;
            s2 += v.x*v.x + v.y*v.y + v.z*v.z + v.w*v.w;
        }
    }
    __shared__ float rs[8], rs2[8];
    int lane = tid & 31, wid = tid >> 5;
    s = warpsum(s); s2 = warpsum(s2);
    if (lane == 0) { rs[wid] = s; rs2[wid] = s2; }
    __syncthreads();
    if (wid == 0) {
        s  = (lane < 8) ? rs[lane]  : 0.f;
        s2 = (lane < 8) ? rs2[lane] : 0.f;
        s = warpsum(s); s2 = warpsum(s2);
        if (lane == 0) {
            float n = (float)(BB*HW);
            float m = s / n;
            float var = s2 / n - m*m;
            float ga = (ch < 64) ? __ldg(gam_off + ch) : __ldg(gam_mod + ch - 64);
            float be = (ch < 64) ? __ldg(bet_off + ch) : __ldg(bet_mod + ch - 64);
            float sc = ga * rsqrtf(var + EPSV);
            g_scale[ch] = sc;
            g_shift[ch] = be - m * sc;
        }
    }
}

// ---------------- conv2: GEMM-ized (M=32, K=1152), BN+SiLU fused ------------
__global__ __launch_bounds__(256) void conv2_t(const float* __restrict__ off_b2,
                                               const float* __restrict__ mod_b2,
                                               float* __restrict__ offs,
                                               float* __restrict__ modu) {
    char* smem_c = smem_dyn;
    uint32_t smem_base = smem_u32(smem_c);
    int tid = threadIdx.x, wid = tid >> 5, lane = tid & 31;
    int blk = blockIdx.x;
    int b = blk >> 7, h = blk & 127;
    float* stg = (float*)(smem_c + C2_OFF_STG);

    int wpx = wid * 16;
    float acc[2][2][4];
    #pragma unroll
    for (int mt = 0; mt < 2; mt++)
        #pragma unroll
        for (int nt = 0; nt < 2; nt++)
            #pragma unroll
            for (int q = 0; q < 4; q++) acc[mt][nt][q] = 0.f;

    int px = tid & 127, kh = tid >> 7;
    if (tid < 48) stg[(tid >> 1)*132 + ((tid & 1) ? 129 : 0)] = 0.f;

    for (int ck = 0; ck < 18; ck++) {
        if (ck) __syncthreads();
        // A chunk (4608 B)
        {
            const uint4* sa = (const uint4*)(g_w2 + (size_t)ck*32*SK);
            uint4* da = (uint4*)(smem_c + C2_OFF_A);
            for (int i = tid; i < 32*SK/8; i += 256) da[i] = sa[i];
        }
        // stage fill with fused BN+SiLU (no forced unroll)
        int ckm = ck % 9;
        int chbase = (ck / 9) * 64;
        int c_lo = (ckm*KC) / 9;
        for (int i = tid; i < 3072; i += 256) {
            int ch = i / 384;
            int rr = (i - ch*384) >> 7;
            int col = i & 127;
            int hh = h + rr - 1;
            int cg = chbase + c_lo + ch;
            float v = 0.f;
            if ((unsigned)hh < H) {
                float raw = __ldg(g_t + ((size_t)(b*COUT) + cg)*HW + hh*W + col);
                raw = raw * g_scale[cg] + g_shift[cg];
                v = silu_f(raw);
            }
            stg[(ch*3 + rr)*132 + 1 + col] = v;
        }
        __syncthreads();
        // B build
        {
            int k0h = ckm*KC + kh*32;
            int c = k0h / 9, t = k0h - 9*c;
            #pragma unroll 8
            for (int kk2 = 0; kk2 < 32; kk2++) {
                int dy = t / 3, dxm = t - dy*3;
                float v = stg[((c - c_lo)*3 + dy)*132 + px + dxm];
                *(unsigned short*)(smem_c + C2_OFF_B + (kh*32 + kk2)*(SKB*2) + px*2) = h_bits(v);
                if (++t == 9) { t = 0; c++; }
            }
        }
        __syncthreads();
        // mma: M=32, warp covers 16 px
        {
            uint32_t baseA = smem_base + C2_OFF_A;
            uint32_t baseB = smem_base + C2_OFF_B;
            #pragma unroll
            for (int ks = 0; ks < 4; ks++) {
                int k0 = ks * 16;
                uint32_t a[2][4];
                ldsm_x4(a[0], a_addr(baseA, 0, k0, lane));
                ldsm_x4(a[1], a_addr(baseA, 16, k0, lane));
                #pragma unroll
                for (int nt = 0; nt < 2; nt++) {
                    uint32_t bh[2];
                    ldsm_x2_t(bh, b_addr_t(baseB, k0, wpx + nt*8, lane));
                    mma_f16(acc[0][nt], a[0], bh);
                    mma_f16(acc[1][nt], a[1], bh);
                }
            }
        }
    }

    // epilogue: rows 0-17 -> offs, rows 18-26 -> sigmoid -> modu
    int g = lane >> 2, tg = lane & 3;
    #pragma unroll
    for (int mt = 0; mt < 2; mt++) {
        #pragma unroll
        for (int half = 0; half < 2; half++) {
            int row = mt*16 + half*8 + g;
            #pragma unroll
            for (int nt = 0; nt < 2; nt++) {
                int p2 = wpx + nt*8 + 2*tg;
                float v0 = acc[mt][nt][half*2 + 0];
                float v1 = acc[mt][nt][half*2 + 1];
                if (row < 18) {
                    float bv = __ldg(off_b2 + row);
                    *(float2*)(offs + ((size_t)(b*18 + row))*HW + h*W + p2) =
                        make_float2(v0 + bv, v1 + bv);
                } else if (row < 27) {
                    float bv = __ldg(mod_b2 + row - 18);
                    float s0 = __fdividef(1.f, 1.f + __expf(-(v0 + bv)));
                    float s1 = __fdividef(1.f, 1.f + __expf(-(v1 + bv)));
                    *(float2*)(modu + ((size_t)(b*9 + row - 18))*HW + h*W + p2) =
                        make_float2(s0, s1);
                }
            }
        }
    }
}

// ---------------- deform: mma GEMM, tap-outer gather producer (R7 form) -----
__global__ __launch_bounds__(256) void deform_t(const float* __restrict__ x,
                                                const float* __restrict__ bias,
                                                float* __restrict__ out) {
    char* smem_c = smem_dyn;
    uint32_t smem_base = smem_u32(smem_c);
    int tid = threadIdx.x, wid = tid >> 5, lane = tid & 31;
    int blk = blockIdx.x;
    int b = blk >> 7, h = blk & 127;
    const float* xb = x + (size_t)b * C * HW;
    float2* sTap = (float2*)(smem_c + OFF_TAP);

    for (int i = tid; i < 9*128; i += 256) {
        int tap = i >> 7, px = i & 127;
        size_t sp = (size_t)h*W + px;
        float offy = __ldg(g_offs + ((size_t)(b*18 + tap*2 + 1))*HW + sp);
        float offx = __ldg(g_offs + ((size_t)(b*18 + tap*2 + 0))*HW + sp);
        float m    = __ldg(g_modu + ((size_t)(b*9 + tap))*HW + sp);
        float sy = (float)h  + (float)(tap/3 - 1) + offy;
        float sx2 = (float)px + (float)(tap%3 - 1) + offx;
        float y0f = floorf(sy), x0f = floorf(sx2);
        int y0 = (int)y0f, x0 = (int)x0f;
        float wy1 = sy - y0f, wx1 = sx2 - x0f;
        float wy0 = 1.f - wy1, wx0 = 1.f - wx1;
        #pragma unroll
        for (int cn = 0; cn < 4; cn++) {
            int yy = y0 + (cn >> 1);
            int xx = x0 + (cn & 1);
            float wgt = ((cn & 2) ? wy1 : wy0) * ((cn & 1) ? wx1 : wx0) * m;
            bool valid = ((unsigned)yy < H) && ((unsigned)xx < W);
            int yc = min(max(yy, 0), H-1);
            int xc = min(max(xx, 0), W-1);
            sTap[(tap*4 + cn)*128 + px] = make_float2(valid ? wgt : 0.f,
                                                      __int_as_float(yc*W + xc));
        }
    }

    int wco = (wid >> 1) * 32;
    int wpx = (wid & 1) * 64;
    float acc[2][8][4];
    #pragma unroll
    for (int mt = 0; mt < 2; mt++)
        #pragma unroll
        for (int nt = 0; nt < 8; nt++)
            #pragma unroll
            for (int q = 0; q < 4; q++) acc[mt][nt][q] = 0.f;

    int px = tid & 127, kh = tid >> 7;
    __syncthreads();

    for (int ck = 0; ck < NCHUNK; ck++) {
        if (ck) __syncthreads();
        {
            const uint4* sa = (const uint4*)(g_w4 + (size_t)ck*COUT*SK);
            uint4* da = (uint4*)(smem_c + OFF_A);
            for (int i = tid; i < COUT*SK/8; i += 256) da[i] = sa[i];
        }
        int k0h = ck*KC + kh*32;
        #pragma unroll
        for (int t = 0; t < 9; t++) {
            float2 t0 = sTap[(t*4 + 0)*128 + px];
            float2 t1 = sTap[(t*4 + 1)*128 + px];
            float2 t2 = sTap[(t*4 + 2)*128 + px];
            float2 t3 = sTap[(t*4 + 3)*128 + px];
            int i0 = __float_as_int(t0.y), i1 = __float_as_int(t1.y);
            int i2 = __float_as_int(t2.y), i3 = __float_as_int(t3.y);
            int clo = (k0h - t + 8) / 9;
            int chi = (k0h + 31 - t) / 9;
            for (int c = clo; c <= chi; c++) {
                const float* xc = xb + (size_t)c*HW;
                float v = t0.x * __ldg(xc + i0);
                v = fmaf(t1.x, __ldg(xc + i1), v);
                v = fmaf(t2.x, __ldg(xc + i2), v);
                v = fmaf(t3.x, __ldg(xc + i3), v);
                int kk = c*9 + t - ck*KC;
                *(unsigned short*)(smem_c + OFF_B + kk*(SKB*2) + px*2) = h_bits(v);
            }
        }
        __syncthreads();
        mma_chunk(smem_base, lane, wco, wpx, acc);
    }

    int g = lane >> 2, tg = lane & 3;
    float* dst = out + (size_t)b*COUT*HW + (size_t)h*W;
    #pragma unroll
    for (int mt = 0; mt < 2; mt++) {
        int co0 = wco + mt*16 + g;
        int co1 = co0 + 8;
        float bv0 = __ldg(bias + co0);
        float bv1 = __ldg(bias + co1);
        #pragma unroll
        for (int nt = 0; nt < 8; nt++) {
            int p2 = wpx + nt*8 + 2*tg;
            *(float2*)(dst + (size_t)co0*HW + p2) = make_float2(acc[mt][nt][0]+bv0, acc[mt][nt][1]+bv0);
            *(float2*)(dst + (size_t)co1*HW + p2) = make_float2(acc[mt][nt][2]+bv1, acc[mt][nt][3]+bv1);
        }
    }
}

// ---------------- launch ----------------
extern "C" void kernel_launch(void* const* d_in, const int* in_sizes, int n_in,
                              void* d_out, int out_size) {
    const float* x        = (const float*)d_in[0];
    const float* weight   = (const float*)d_in[1];
    const float* bias     = (const float*)d_in[2];
    const float* off_w1   = (const float*)d_in[3];
    const float* off_b1   = (const float*)d_in[4];
    const float* off_g    = (const float*)d_in[5];
    const float* off_be   = (const float*)d_in[6];
    const float* off_w2   = (const float*)d_in[7];
    const float* off_b2   = (const float*)d_in[8];
    const float* mod_w1   = (const float*)d_in[9];
    const float* mod_b1   = (const float*)d_in[10];
    const float* mod_g    = (const float*)d_in[11];
    const float* mod_be   = (const float*)d_in[12];
    const float* mod_w2   = (const float*)d_in[13];
    const float* mod_b2   = (const float*)d_in[14];
    float* out = (float*)d_out;

    cudaFuncSetAttribute(conv1_t, cudaFuncAttributeMaxDynamicSharedMemorySize, SMEM_C1);
    cudaFuncSetAttribute(conv2_t, cudaFuncAttributeMaxDynamicSharedMemorySize, SMEM_C2);
    cudaFuncSetAttribute(deform_t, cudaFuncAttributeMaxDynamicSharedMemorySize, SMEM_DEF);

    float *offs_ptr, *modu_ptr;
    cudaGetSymbolAddress((void**)&offs_ptr, g_offs);
    cudaGetSymbolAddress((void**)&modu_ptr, g_modu);

    prep_weights<<<(NCHUNK*COUT*KC + 255)/256, 256>>>(off_w1, mod_w1, weight);
    prep_w2<<<(18*32*KC + 255)/256, 256>>>(off_w2, mod_w2);
    conv1_t<<<1024, 256, SMEM_C1>>>(x, off_b1, mod_b1);
    bn_stats<<<128, 256>>>(off_g, off_be, mod_g, mod_be);
    conv2_t<<<1024, 256, SMEM_C2>>>(off_b2, mod_b2, offs_ptr, modu_ptr);
    deform_t<<<1024, 256, SMEM_DEF>>>(x, bias, out);
}

// round 13
// speedup vs baseline: 1.0451x; 1.0451x over previous
#include <cuda_runtime.h>
#include <cuda_fp16.h>
#include <math.h>
#include <stdint.h>

#define BB 8
#define C 64
#define COUT 128
#define H 128
#define W 128
#define HW (H*W)
#define KC 64
#define NCHUNK 9
#define SK 72              // A smem k-stride (fp16): 144B rows, conflict-free ldmatrix
#define SKB 136            // B smem px-stride (fp16): 272B rows, conflict-free trans ldmatrix
#define EPSV 1e-5f

// ---------------- smem layouts (byte offsets) ----------------
// conv1 / deform:
#define OFF_A   0                       // 128*72*2  = 18432
#define OFF_B   18432                   // 64*136*2  = 17408
#define OFF_STG 35840                   // conv1: float [8][3][132] = 12672
#define SMEM_C1 (35840 + 12672)         // 48512
#define OFF_TAP 35840                   // deform: float2 [36][128] = 36864
#define SMEM_DEF (35840 + 36864)        // 72704
// conv2 (GEMM-ized, direct fp16 loads):
#define C2_OFF_A   0                    // 32*72*2 = 4608
#define C2_OFF_B   4608                 // 64*136*2 = 17408
#define SMEM_C2    22016

// ---------------- device scratch (POD types only) ----------------
__device__ float g_t[BB*2*C*HW];
__device__ __align__(16) unsigned short g_acth[BB*COUT*HW];   // silu(bn(g_t)) as fp16 bits
__device__ float g_offs[BB*18*HW];
__device__ float g_modu[BB*9*HW];
__device__ float g_scale[2*C];
__device__ float g_shift[2*C];
__device__ __align__(16) unsigned short g_w1[NCHUNK*COUT*SK];
__device__ __align__(16) unsigned short g_w4[NCHUNK*COUT*SK];
__device__ __align__(16) unsigned short g_w2[18*32*SK];   // conv2 block-diag A

// ---------------- helpers ----------------
__device__ __forceinline__ uint32_t smem_u32(const void* p) {
    uint32_t a;
    asm("{ .reg .u64 t; cvta.to.shared.u64 t, %1; cvt.u32.u64 %0, t; }" : "=r"(a) : "l"(p));
    return a;
}
__device__ __forceinline__ unsigned short h_bits(float v) {
    __half h = __float2half_rn(v);
    return *reinterpret_cast<unsigned short*>(&h);
}
__device__ __forceinline__ void ldsm_x4(uint32_t a[4], uint32_t addr) {
    asm volatile("ldmatrix.sync.aligned.m8n8.x4.shared.b16 {%0,%1,%2,%3}, [%4];"
        : "=r"(a[0]), "=r"(a[1]), "=r"(a[2]), "=r"(a[3]) : "r"(addr));
}
__device__ __forceinline__ void ldsm_x2_t(uint32_t b[2], uint32_t addr) {
    asm volatile("ldmatrix.sync.aligned.m8n8.x2.trans.shared.b16 {%0,%1}, [%2];"
        : "=r"(b[0]), "=r"(b[1]) : "r"(addr));
}
__device__ __forceinline__ void mma_f16(float d[4], const uint32_t a[4], const uint32_t b[2]) {
    asm volatile("mma.sync.aligned.m16n8k16.row.col.f32.f16.f16.f32 "
        "{%0,%1,%2,%3}, {%4,%5,%6,%7}, {%8,%9}, {%0,%1,%2,%3};"
        : "+f"(d[0]), "+f"(d[1]), "+f"(d[2]), "+f"(d[3])
        : "r"(a[0]), "r"(a[1]), "r"(a[2]), "r"(a[3]), "r"(b[0]), "r"(b[1]));
}
__device__ __forceinline__ uint32_t a_addr(uint32_t base, int row0, int k0, int lane) {
    int q = lane >> 3;
    int row = row0 + (lane & 7) + (q & 1) * 8;
    int col = k0 + (q >> 1) * 8;
    return base + (uint32_t)(row * SK + col) * 2u;
}
__device__ __forceinline__ uint32_t b_addr_t(uint32_t base, int k0, int n0, int lane) {
    int row = k0 + (lane & 15);
    return base + (uint32_t)(row * SKB + n0) * 2u;
}
__device__ __forceinline__ float silu_f(float v) {
    return __fdividef(v, 1.f + __expf(-v));
}

// ---------------- weight prep ----------------
__global__ void prep_weights(const float* __restrict__ off_w1,
                             const float* __restrict__ mod_w1,
                             const float* __restrict__ wmain) {
    int i = blockIdx.x * 256 + threadIdx.x;
    if (i >= NCHUNK*COUT*KC) return;
    int ck = i / (COUT*KC);
    int r  = i - ck*(COUT*KC);
    int co = r >> 6;
    int j  = r & 63;
    int k = ck*KC + j;
    int c = k / 9, t = k - c*9;
    size_t soff = (size_t)(ck*COUT + co)*SK + j;
    float w1 = (co < 64) ? off_w1[(co*C + c)*9 + t] : mod_w1[((co-64)*C + c)*9 + t];
    g_w1[soff] = h_bits(w1);
    g_w4[soff] = h_bits(wmain[(co*C + c)*9 + t]);
}

__global__ void prep_w2(const float* __restrict__ off_w2,
                        const float* __restrict__ mod_w2) {
    int i = blockIdx.x * 256 + threadIdx.x;
    if (i >= 18*32*KC) return;
    int ck = i / (32*KC);
    int r  = i - ck*(32*KC);
    int row = r >> 6;
    int j   = r & 63;
    int kb = (ck % 9)*KC + j;
    int c = kb / 9, t = kb - c*9;
    int branch = ck / 9;
    float w = 0.f;
    if (branch == 0 && row < 18)       w = off_w2[(row*C + c)*9 + t];
    else if (branch == 1 && row >= 18 && row < 27) w = mod_w2[((row-18)*C + c)*9 + t];
    g_w2[(size_t)(ck*32 + row)*SK + j] = h_bits(w);
}

extern __shared__ char smem_dyn[];

// ---------------- shared GEMM consumer (M=128 variant) ----------------
__device__ __forceinline__ void mma_chunk(uint32_t smem_base, int lane, int wco, int wpx,
                                          float acc[2][8][4]) {
    uint32_t baseA = smem_base + OFF_A;
    uint32_t baseB = smem_base + OFF_B;
    #pragma unroll
    for (int ks = 0; ks < 4; ks++) {
        int k0 = ks * 16;
        uint32_t a[2][4];
        #pragma unroll
        for (int mt = 0; mt < 2; mt++)
            ldsm_x4(a[mt], a_addr(baseA, wco + mt*16, k0, lane));
        #pragma unroll
        for (int nt = 0; nt < 8; nt++) {
            uint32_t bh[2];
            ldsm_x2_t(bh, b_addr_t(baseB, k0, wpx + nt*8, lane));
            #pragma unroll
            for (int mt = 0; mt < 2; mt++)
                mma_f16(acc[mt][nt], a[mt], bh);
        }
    }
}

// ---------------- conv1: mma GEMM, smem-staged im2col producer --------------
__global__ __launch_bounds__(256) void conv1_t(const float* __restrict__ x,
                                               const float* __restrict__ b_off,
                                               const float* __restrict__ b_mod) {
    char* smem_c = smem_dyn;
    uint32_t smem_base = smem_u32(smem_c);
    int tid = threadIdx.x, wid = tid >> 5, lane = tid & 31;
    int blk = blockIdx.x;
    int b = blk >> 7, h = blk & 127;
    const float* xb = x + (size_t)b * C * HW;
    float* stg = (float*)(smem_c + OFF_STG);

    int wco = (wid >> 1) * 32;
    int wpx = (wid & 1) * 64;
    float acc[2][8][4];
    #pragma unroll
    for (int mt = 0; mt < 2; mt++)
        #pragma unroll
        for (int nt = 0; nt < 8; nt++)
            #pragma unroll
            for (int q = 0; q < 4; q++) acc[mt][nt][q] = 0.f;

    int px = tid & 127, kh = tid >> 7;
    if (tid < 48) stg[(tid >> 1)*132 + ((tid & 1) ? 129 : 0)] = 0.f;

    for (int ck = 0; ck < NCHUNK; ck++) {
        if (ck) __syncthreads();
        {
            const uint4* sa = (const uint4*)(g_w1 + (size_t)ck*COUT*SK);
            uint4* da = (uint4*)(smem_c + OFF_A);
            for (int i = tid; i < COUT*SK/8; i += 256) da[i] = sa[i];
        }
        int c_lo = (ck*KC) / 9;
        #pragma unroll
        for (int it = 0; it < 12; it++) {
            int i = it*256 + tid;
            int ch = i / 384;
            int rr = (i - ch*384) >> 7;
            int col = i & 127;
            int hh = h + rr - 1;
            float v = ((unsigned)hh < H) ? __ldg(xb + (size_t)(c_lo + ch)*HW + hh*W + col) : 0.f;
            stg[(ch*3 + rr)*132 + 1 + col] = v;
        }
        __syncthreads();
        {
            int k0h = ck*KC + kh*32;
            int c = k0h / 9, t = k0h - 9*c;
            #pragma unroll 8
            for (int kk2 = 0; kk2 < 32; kk2++) {
                int dy = t / 3, dxm = t - dy*3;
                float v = stg[((c - c_lo)*3 + dy)*132 + px + dxm];
                *(unsigned short*)(smem_c + OFF_B + (kh*32 + kk2)*(SKB*2) + px*2) = h_bits(v);
                if (++t == 9) { t = 0; c++; }
            }
        }
        __syncthreads();
        mma_chunk(smem_base, lane, wco, wpx, acc);
    }

    int g = lane >> 2, tg = lane & 3;
    float* dst = g_t + (size_t)b*COUT*HW + (size_t)h*W;
    #pragma unroll
    for (int mt = 0; mt < 2; mt++) {
        int co0 = wco + mt*16 + g;
        int co1 = co0 + 8;
        float bv0 = (co0 < 64) ? __ldg(b_off + co0) : __ldg(b_mod + co0 - 64);
        float bv1 = (co1 < 64) ? __ldg(b_off + co1) : __ldg(b_mod + co1 - 64);
        #pragma unroll
        for (int nt = 0; nt < 8; nt++) {
            int p2 = wpx + nt*8 + 2*tg;
            *(float2*)(dst + (size_t)co0*HW + p2) = make_float2(acc[mt][nt][0]+bv0, acc[mt][nt][1]+bv0);
            *(float2*)(dst + (size_t)co1*HW + p2) = make_float2(acc[mt][nt][2]+bv1, acc[mt][nt][3]+bv1);
        }
    }
}

// ---------------- BN stats ----------------
__inline__ __device__ float warpsum(float v) {
    #pragma unroll
    for (int o = 16; o; o >>= 1) v += __shfl_down_sync(0xFFFFFFFFu, v, o);
    return v;
}

__global__ __launch_bounds__(256) void bn_stats(const float* __restrict__ gam_off,
                                                const float* __restrict__ bet_off,
                                                const float* __restrict__ gam_mod,
                                                const float* __restrict__ bet_mod) {
    int ch = blockIdx.x;
    int tid = threadIdx.x;
    float s = 0.f, s2 = 0.f;
    for (int b = 0; b < BB; b++) {
        const float4* p = (const float4*)(g_t + ((size_t)(b*2*C + ch))*HW);
        for (int i = tid; i < HW/4; i += 256) {
            float4 v = p[i];
            s  += v.x + v.y + v.z + v.w;
            s2 += v.x*v.x + v.y*v.y + v.z*v.z + v.w*v.w;
        }
    }
    __shared__ float rs[8], rs2[8];
    int lane = tid & 31, wid = tid >> 5;
    s = warpsum(s); s2 = warpsum(s2);
    if (lane == 0) { rs[wid] = s; rs2[wid] = s2; }
    __syncthreads();
    if (wid == 0) {
        s  = (lane < 8) ? rs[lane]  : 0.f;
        s2 = (lane < 8) ? rs2[lane] : 0.f;
        s = warpsum(s); s2 = warpsum(s2);
        if (lane == 0) {
            float n = (float)(BB*HW);
            float m = s / n;
            float var = s2 / n - m*m;
            float ga = (ch < 64) ? __ldg(gam_off + ch) : __ldg(gam_mod + ch - 64);
            float be = (ch < 64) ? __ldg(bet_off + ch) : __ldg(bet_mod + ch - 64);
            float sc = ga * rsqrtf(var + EPSV);
            g_scale[ch] = sc;
            g_shift[ch] = be - m * sc;
        }
    }
}

// ---------------- BN apply + SiLU -> fp16 bits (one silu per value) ---------
__global__ __launch_bounds__(256) void bn_act_h() {
    int n4 = BB*2*C*HW/4;
    for (int i = blockIdx.x*blockDim.x + threadIdx.x; i < n4; i += gridDim.x*blockDim.x) {
        int c = (i >> 12) & 127;   // HW/4 = 4096 quads per channel
        float sc = g_scale[c], sh = g_shift[c];
        float4 v = ((const float4*)g_t)[i];
        v.x = silu_f(v.x*sc + sh);
        v.y = silu_f(v.y*sc + sh);
        v.z = silu_f(v.z*sc + sh);
        v.w = silu_f(v.w*sc + sh);
        uint2 pk;
        pk.x = (uint32_t)h_bits(v.x) | ((uint32_t)h_bits(v.y) << 16);
        pk.y = (uint32_t)h_bits(v.z) | ((uint32_t)h_bits(v.w) << 16);
        ((uint2*)g_acth)[i] = pk;
    }
}

// ---------------- conv2: GEMM-ized, direct fp16 activation loads ------------
__global__ __launch_bounds__(256) void conv2_t(const float* __restrict__ off_b2,
                                               const float* __restrict__ mod_b2,
                                               float* __restrict__ offs,
                                               float* __restrict__ modu) {
    char* smem_c = smem_dyn;
    uint32_t smem_base = smem_u32(smem_c);
    int tid = threadIdx.x, wid = tid >> 5, lane = tid & 31;
    int blk = blockIdx.x;
    int b = blk >> 7, h = blk & 127;

    int wpx = wid * 16;
    float acc[2][2][4];
    #pragma unroll
    for (int mt = 0; mt < 2; mt++)
        #pragma unroll
        for (int nt = 0; nt < 2; nt++)
            #pragma unroll
            for (int q = 0; q < 4; q++) acc[mt][nt][q] = 0.f;

    int px = tid & 127, kh = tid >> 7;

    for (int ck = 0; ck < 18; ck++) {
        if (ck) __syncthreads();
        // A chunk (4608 B)
        {
            const uint4* sa = (const uint4*)(g_w2 + (size_t)ck*32*SK);
            uint4* da = (uint4*)(smem_c + C2_OFF_A);
            for (int i = tid; i < 32*SK/8; i += 256) da[i] = sa[i];
        }
        // B build: direct coalesced fp16-bit loads (no silu, no stage)
        {
            int ckm = ck % 9;
            int branch = ck / 9;
            const unsigned short* ab = g_acth + ((size_t)(b*COUT) + branch*64)*HW;
            int k0h = ckm*KC + kh*32;
            int c = k0h / 9, t = k0h - 9*c;
            #pragma unroll 8
            for (int kk2 = 0; kk2 < 32; kk2++) {
                int dy = t / 3, dxm = t - dy*3;
                int hh = h + dy - 1, ww = px + dxm - 1;
                unsigned short v = 0;
                if ((unsigned)hh < H && (unsigned)ww < W)
                    v = __ldg(ab + (size_t)c*HW + hh*W + ww);
                *(unsigned short*)(smem_c + C2_OFF_B + (kh*32 + kk2)*(SKB*2) + px*2) = v;
                if (++t == 9) { t = 0; c++; }
            }
        }
        __syncthreads();
        // mma: M=32, warp covers 16 px
        {
            uint32_t baseA = smem_base + C2_OFF_A;
            uint32_t baseB = smem_base + C2_OFF_B;
            #pragma unroll
            for (int ks = 0; ks < 4; ks++) {
                int k0 = ks * 16;
                uint32_t a[2][4];
                ldsm_x4(a[0], a_addr(baseA, 0, k0, lane));
                ldsm_x4(a[1], a_addr(baseA, 16, k0, lane));
                #pragma unroll
                for (int nt = 0; nt < 2; nt++) {
                    uint32_t bh[2];
                    ldsm_x2_t(bh, b_addr_t(baseB, k0, wpx + nt*8, lane));
                    mma_f16(acc[0][nt], a[0], bh);
                    mma_f16(acc[1][nt], a[1], bh);
                }
            }
        }
    }

    // epilogue: rows 0-17 -> offs, rows 18-26 -> sigmoid -> modu
    int g = lane >> 2, tg = lane & 3;
    #pragma unroll
    for (int mt = 0; mt < 2; mt++) {
        #pragma unroll
        for (int half = 0; half < 2; half++) {
            int row = mt*16 + half*8 + g;
            #pragma unroll
            for (int nt = 0; nt < 2; nt++) {
                int p2 = wpx + nt*8 + 2*tg;
                float v0 = acc[mt][nt][half*2 + 0];
                float v1 = acc[mt][nt][half*2 + 1];
                if (row < 18) {
                    float bv = __ldg(off_b2 + row);
                    *(float2*)(offs + ((size_t)(b*18 + row))*HW + h*W + p2) =
                        make_float2(v0 + bv, v1 + bv);
                } else if (row < 27) {
                    float bv = __ldg(mod_b2 + row - 18);
                    float s0 = __fdividef(1.f, 1.f + __expf(-(v0 + bv)));
                    float s1 = __fdividef(1.f, 1.f + __expf(-(v1 + bv)));
                    *(float2*)(modu + ((size_t)(b*9 + row - 18))*HW + h*W + p2) =
                        make_float2(s0, s1);
                }
            }
        }
    }
}

// ---------------- deform: mma GEMM, tap-outer gather producer (R7 form) -----
__global__ __launch_bounds__(256) void deform_t(const float* __restrict__ x,
                                                const float* __restrict__ bias,
                                                float* __restrict__ out) {
    char* smem_c = smem_dyn;
    uint32_t smem_base = smem_u32(smem_c);
    int tid = threadIdx.x, wid = tid >> 5, lane = tid & 31;
    int blk = blockIdx.x;
    int b = blk >> 7, h = blk & 127;
    const float* xb = x + (size_t)b * C * HW;
    float2* sTap = (float2*)(smem_c + OFF_TAP);

    for (int i = tid; i < 9*128; i += 256) {
        int tap = i >> 7, px = i & 127;
        size_t sp = (size_t)h*W + px;
        float offy = __ldg(g_offs + ((size_t)(b*18 + tap*2 + 1))*HW + sp);
        float offx = __ldg(g_offs + ((size_t)(b*18 + tap*2 + 0))*HW + sp);
        float m    = __ldg(g_modu + ((size_t)(b*9 + tap))*HW + sp);
        float sy = (float)h  + (float)(tap/3 - 1) + offy;
        float sx2 = (float)px + (float)(tap%3 - 1) + offx;
        float y0f = floorf(sy), x0f = floorf(sx2);
        int y0 = (int)y0f, x0 = (int)x0f;
        float wy1 = sy - y0f, wx1 = sx2 - x0f;
        float wy0 = 1.f - wy1, wx0 = 1.f - wx1;
        #pragma unroll
        for (int cn = 0; cn < 4; cn++) {
            int yy = y0 + (cn >> 1);
            int xx = x0 + (cn & 1);
            float wgt = ((cn & 2) ? wy1 : wy0) * ((cn & 1) ? wx1 : wx0) * m;
            bool valid = ((unsigned)yy < H) && ((unsigned)xx < W);
            int yc = min(max(yy, 0), H-1);
            int xc = min(max(xx, 0), W-1);
            sTap[(tap*4 + cn)*128 + px] = make_float2(valid ? wgt : 0.f,
                                                      __int_as_float(yc*W + xc));
        }
    }

    int wco = (wid >> 1) * 32;
    int wpx = (wid & 1) * 64;
    float acc[2][8][4];
    #pragma unroll
    for (int mt = 0; mt < 2; mt++)
        #pragma unroll
        for (int nt = 0; nt < 8; nt++)
            #pragma unroll
            for (int q = 0; q < 4; q++) acc[mt][nt][q] = 0.f;

    int px = tid & 127, kh = tid >> 7;
    __syncthreads();

    for (int ck = 0; ck < NCHUNK; ck++) {
        if (ck) __syncthreads();
        {
            const uint4* sa = (const uint4*)(g_w4 + (size_t)ck*COUT*SK);
            uint4* da = (uint4*)(smem_c + OFF_A);
            for (int i = tid; i < COUT*SK/8; i += 256) da[i] = sa[i];
        }
        int k0h = ck*KC + kh*32;
        #pragma unroll
        for (int t = 0; t < 9; t++) {
            float2 t0 = sTap[(t*4 + 0)*128 + px];
            float2 t1 = sTap[(t*4 + 1)*128 + px];
            float2 t2 = sTap[(t*4 + 2)*128 + px];
            float2 t3 = sTap[(t*4 + 3)*128 + px];
            int i0 = __float_as_int(t0.y), i1 = __float_as_int(t1.y);
            int i2 = __float_as_int(t2.y), i3 = __float_as_int(t3.y);
            int clo = (k0h - t + 8) / 9;
            int chi = (k0h + 31 - t) / 9;
            for (int c = clo; c <= chi; c++) {
                const float* xc = xb + (size_t)c*HW;
                float v = t0.x * __ldg(xc + i0);
                v = fmaf(t1.x, __ldg(xc + i1), v);
                v = fmaf(t2.x, __ldg(xc + i2), v);
                v = fmaf(t3.x, __ldg(xc + i3), v);
                int kk = c*9 + t - ck*KC;
                *(unsigned short*)(smem_c + OFF_B + kk*(SKB*2) + px*2) = h_bits(v);
            }
        }
        __syncthreads();
        mma_chunk(smem_base, lane, wco, wpx, acc);
    }

    int g = lane >> 2, tg = lane & 3;
    float* dst = out + (size_t)b*COUT*HW + (size_t)h*W;
    #pragma unroll
    for (int mt = 0; mt < 2; mt++) {
        int co0 = wco + mt*16 + g;
        int co1 = co0 + 8;
        float bv0 = __ldg(bias + co0);
        float bv1 = __ldg(bias + co1);
        #pragma unroll
        for (int nt = 0; nt < 8; nt++) {
            int p2 = wpx + nt*8 + 2*tg;
            *(float2*)(dst + (size_t)co0*HW + p2) = make_float2(acc[mt][nt][0]+bv0, acc[mt][nt][1]+bv0);
            *(float2*)(dst + (size_t)co1*HW + p2) = make_float2(acc[mt][nt][2]+bv1, acc[mt][nt][3]+bv1);
        }
    }
}

// ---------------- launch ----------------
extern "C" void kernel_launch(void* const* d_in, const int* in_sizes, int n_in,
                              void* d_out, int out_size) {
    const float* x        = (const float*)d_in[0];
    const float* weight   = (const float*)d_in[1];
    const float* bias     = (const float*)d_in[2];
    const float* off_w1   = (const float*)d_in[3];
    const float* off_b1   = (const float*)d_in[4];
    const float* off_g    = (const float*)d_in[5];
    const float* off_be   = (const float*)d_in[6];
    const float* off_w2   = (const float*)d_in[7];
    const float* off_b2   = (const float*)d_in[8];
    const float* mod_w1   = (const float*)d_in[9];
    const float* mod_b1   = (const float*)d_in[10];
    const float* mod_g    = (const float*)d_in[11];
    const float* mod_be   = (const float*)d_in[12];
    const float* mod_w2   = (const float*)d_in[13];
    const float* mod_b2   = (const float*)d_in[14];
    float* out = (float*)d_out;

    cudaFuncSetAttribute(conv1_t, cudaFuncAttributeMaxDynamicSharedMemorySize, SMEM_C1);
    cudaFuncSetAttribute(conv2_t, cudaFuncAttributeMaxDynamicSharedMemorySize, SMEM_C2);
    cudaFuncSetAttribute(deform_t, cudaFuncAttributeMaxDynamicSharedMemorySize, SMEM_DEF);

    float *offs_ptr, *modu_ptr;
    cudaGetSymbolAddress((void**)&offs_ptr, g_offs);
    cudaGetSymbolAddress((void**)&modu_ptr, g_modu);

    prep_weights<<<(NCHUNK*COUT*KC + 255)/256, 256>>>(off_w1, mod_w1, weight);
    prep_w2<<<(18*32*KC + 255)/256, 256>>>(off_w2, mod_w2);
    conv1_t<<<1024, 256, SMEM_C1>>>(x, off_b1, mod_b1);
    bn_stats<<<128, 256>>>(off_g, off_be, mod_g, mod_be);
    bn_act_h<<<8192, 256>>>();
    conv2_t<<<1024, 256, SMEM_C2>>>(off_b2, mod_b2, offs_ptr, modu_ptr);
    deform_t<<<1024, 256, SMEM_DEF>>>(x, bias, out);
}

// round 14
// speedup vs baseline: 1.0685x; 1.0224x over previous
#include <cuda_runtime.h>
#include <cuda_fp16.h>
#include <math.h>
#include <stdint.h>

#define BB 8
#define C 64
#define COUT 128
#define H 128
#define W 128
#define HW (H*W)
#define KC 64
#define NCHUNK 9
#define SK 72              // A smem k-stride (fp16): 144B rows, conflict-free ldmatrix
#define SKB 136            // B smem px-stride (fp16): 272B rows, conflict-free trans ldmatrix
#define XPW 132            // xpair row width (u32 entries)
#define EPSV 1e-5f

// ---------------- smem layouts (byte offsets) ----------------
// conv1 (no stage now) / deform:
#define OFF_A   0                       // 128*72*2  = 18432
#define OFF_B   18432                   // 64*136*2  = 17408
#define SMEM_C1 35840
#define OFF_TW4 35840                   // deform: float4 [9][128] = 18432
#define OFF_TI2 (35840 + 18432)         // deform: int2   [9][128] = 9216
#define SMEM_DEF (OFF_TI2 + 9216)       // 63488
// conv2 (GEMM-ized, direct fp16 loads):
#define C2_OFF_A   0                    // 32*72*2 = 4608
#define C2_OFF_B   4608                 // 64*136*2 = 17408
#define SMEM_C2    22016

// ---------------- device scratch (POD types only) ----------------
__device__ float g_t[BB*2*C*HW];
__device__ __align__(16) unsigned short g_acth[BB*COUT*HW];   // silu(bn) fp16 bits
__device__ __align__(16) uint32_t g_xp[BB*C*H*XPW];           // paired fp16 x
__device__ float g_offs[BB*18*HW];
__device__ float g_modu[BB*9*HW];
__device__ float g_scale[2*C];
__device__ float g_shift[2*C];
__device__ __align__(16) unsigned short g_w1[NCHUNK*COUT*SK];
__device__ __align__(16) unsigned short g_w4[NCHUNK*COUT*SK];
__device__ __align__(16) unsigned short g_w2[18*32*SK];   // conv2 block-diag A

// ---------------- helpers ----------------
__device__ __forceinline__ uint32_t smem_u32(const void* p) {
    uint32_t a;
    asm("{ .reg .u64 t; cvta.to.shared.u64 t, %1; cvt.u32.u64 %0, t; }" : "=r"(a) : "l"(p));
    return a;
}
__device__ __forceinline__ unsigned short h_bits(float v) {
    __half h = __float2half_rn(v);
    return *reinterpret_cast<unsigned short*>(&h);
}
__device__ __forceinline__ void ldsm_x4(uint32_t a[4], uint32_t addr) {
    asm volatile("ldmatrix.sync.aligned.m8n8.x4.shared.b16 {%0,%1,%2,%3}, [%4];"
        : "=r"(a[0]), "=r"(a[1]), "=r"(a[2]), "=r"(a[3]) : "r"(addr));
}
__device__ __forceinline__ void ldsm_x2_t(uint32_t b[2], uint32_t addr) {
    asm volatile("ldmatrix.sync.aligned.m8n8.x2.trans.shared.b16 {%0,%1}, [%2];"
        : "=r"(b[0]), "=r"(b[1]) : "r"(addr));
}
__device__ __forceinline__ void mma_f16(float d[4], const uint32_t a[4], const uint32_t b[2]) {
    asm volatile("mma.sync.aligned.m16n8k16.row.col.f32.f16.f16.f32 "
        "{%0,%1,%2,%3}, {%4,%5,%6,%7}, {%8,%9}, {%0,%1,%2,%3};"
        : "+f"(d[0]), "+f"(d[1]), "+f"(d[2]), "+f"(d[3])
        : "r"(a[0]), "r"(a[1]), "r"(a[2]), "r"(a[3]), "r"(b[0]), "r"(b[1]));
}
__device__ __forceinline__ uint32_t a_addr(uint32_t base, int row0, int k0, int lane) {
    int q = lane >> 3;
    int row = row0 + (lane & 7) + (q & 1) * 8;
    int col = k0 + (q >> 1) * 8;
    return base + (uint32_t)(row * SK + col) * 2u;
}
__device__ __forceinline__ uint32_t b_addr_t(uint32_t base, int k0, int n0, int lane) {
    int row = k0 + (lane & 15);
    return base + (uint32_t)(row * SKB + n0) * 2u;
}
__device__ __forceinline__ float silu_f(float v) {
    return __fdividef(v, 1.f + __expf(-v));
}
__device__ __forceinline__ float2 up2(uint32_t u) {
    __half2 hv = *reinterpret_cast<__half2*>(&u);
    return __half22float2(hv);
}

// ---------------- weight prep ----------------
__global__ void prep_weights(const float* __restrict__ off_w1,
                             const float* __restrict__ mod_w1,
                             const float* __restrict__ wmain) {
    int i = blockIdx.x * 256 + threadIdx.x;
    if (i >= NCHUNK*COUT*KC) return;
    int ck = i / (COUT*KC);
    int r  = i - ck*(COUT*KC);
    int co = r >> 6;
    int j  = r & 63;
    int k = ck*KC + j;
    int c = k / 9, t = k - c*9;
    size_t soff = (size_t)(ck*COUT + co)*SK + j;
    float w1 = (co < 64) ? off_w1[(co*C + c)*9 + t] : mod_w1[((co-64)*C + c)*9 + t];
    g_w1[soff] = h_bits(w1);
    g_w4[soff] = h_bits(wmain[(co*C + c)*9 + t]);
}

__global__ void prep_w2(const float* __restrict__ off_w2,
                        const float* __restrict__ mod_w2) {
    int i = blockIdx.x * 256 + threadIdx.x;
    if (i >= 18*32*KC) return;
    int ck = i / (32*KC);
    int r  = i - ck*(32*KC);
    int row = r >> 6;
    int j   = r & 63;
    int kb = (ck % 9)*KC + j;
    int c = kb / 9, t = kb - c*9;
    int branch = ck / 9;
    float w = 0.f;
    if (branch == 0 && row < 18)       w = off_w2[(row*C + c)*9 + t];
    else if (branch == 1 && row >= 18 && row < 27) w = mod_w2[((row-18)*C + c)*9 + t];
    g_w2[(size_t)(ck*32 + row)*SK + j] = h_bits(w);
}

// ---------------- xpair prep: g_xp[row][i] = (fp16 v(i-1), fp16 v(i)) -------
__global__ __launch_bounds__(256) void prep_xpair(const float* __restrict__ x) {
    int n = BB*C*H*XPW;
    for (int e = blockIdx.x*blockDim.x + threadIdx.x; e < n; e += gridDim.x*blockDim.x) {
        int row = e / XPW;           // (b*64+c)*128 + y
        int ip  = e - row*XPW;
        const float* xr = x + (size_t)row * W;
        float lo = (ip >= 1 && ip <= 128) ? __ldg(xr + ip - 1) : 0.f;
        float hi = (ip <= 127)            ? __ldg(xr + ip)     : 0.f;
        g_xp[e] = (uint32_t)h_bits(lo) | ((uint32_t)h_bits(hi) << 16);
    }
}

extern __shared__ char smem_dyn[];

// ---------------- shared GEMM consumer (M=128 variant) ----------------
__device__ __forceinline__ void mma_chunk(uint32_t smem_base, int lane, int wco, int wpx,
                                          float acc[2][8][4]) {
    uint32_t baseA = smem_base + OFF_A;
    uint32_t baseB = smem_base + OFF_B;
    #pragma unroll
    for (int ks = 0; ks < 4; ks++) {
        int k0 = ks * 16;
        uint32_t a[2][4];
        #pragma unroll
        for (int mt = 0; mt < 2; mt++)
            ldsm_x4(a[mt], a_addr(baseA, wco + mt*16, k0, lane));
        #pragma unroll
        for (int nt = 0; nt < 8; nt++) {
            uint32_t bh[2];
            ldsm_x2_t(bh, b_addr_t(baseB, k0, wpx + nt*8, lane));
            #pragma unroll
            for (int mt = 0; mt < 2; mt++)
                mma_f16(acc[mt][nt], a[mt], bh);
        }
    }
}

// ---------------- conv1: mma GEMM, direct xpair im2col producer -------------
__global__ __launch_bounds__(256) void conv1_t(const float* __restrict__ b_off,
                                               const float* __restrict__ b_mod) {
    char* smem_c = smem_dyn;
    uint32_t smem_base = smem_u32(smem_c);
    int tid = threadIdx.x, wid = tid >> 5, lane = tid & 31;
    int blk = blockIdx.x;
    int b = blk >> 7, h = blk & 127;

    int wco = (wid >> 1) * 32;
    int wpx = (wid & 1) * 64;
    float acc[2][8][4];
    #pragma unroll
    for (int mt = 0; mt < 2; mt++)
        #pragma unroll
        for (int nt = 0; nt < 8; nt++)
            #pragma unroll
            for (int q = 0; q < 4; q++) acc[mt][nt][q] = 0.f;

    int pxp = tid & 63;        // px pair: covers px 2*pxp, 2*pxp+1
    int kq  = tid >> 6;        // 0..3, each handles 16 k

    for (int ck = 0; ck < NCHUNK; ck++) {
        if (ck) __syncthreads();
        // A tile (fp16 weights)
        {
            const uint4* sa = (const uint4*)(g_w1 + (size_t)ck*COUT*SK);
            uint4* da = (uint4*)(smem_c + OFF_A);
            for (int i = tid; i < COUT*SK/8; i += 256) da[i] = sa[i];
        }
        // B tile: one LDG.32 per (k, px-pair) from g_xp
        {
            int kbase = kq*16;
            int kk = ck*KC + kbase;
            int c = kk / 9, t = kk - 9*c;
            #pragma unroll 8
            for (int j = 0; j < 16; j++) {
                int dy = t / 3, dxm = t - dy*3;
                int hh = h + dy - 1;
                uint32_t v = 0;
                if ((unsigned)hh < H)
                    v = __ldg(g_xp + ((size_t)((b*C + c)*H + hh))*XPW + 2*pxp + dxm);
                *(uint32_t*)(smem_c + OFF_B + (kbase + j)*(SKB*2) + pxp*4) = v;
                if (++t == 9) { t = 0; c++; }
            }
        }
        __syncthreads();
        mma_chunk(smem_base, lane, wco, wpx, acc);
    }

    int g = lane >> 2, tg = lane & 3;
    float* dst = g_t + (size_t)b*COUT*HW + (size_t)h*W;
    #pragma unroll
    for (int mt = 0; mt < 2; mt++) {
        int co0 = wco + mt*16 + g;
        int co1 = co0 + 8;
        float bv0 = (co0 < 64) ? __ldg(b_off + co0) : __ldg(b_mod + co0 - 64);
        float bv1 = (co1 < 64) ? __ldg(b_off + co1) : __ldg(b_mod + co1 - 64);
        #pragma unroll
        for (int nt = 0; nt < 8; nt++) {
            int p2 = wpx + nt*8 + 2*tg;
            *(float2*)(dst + (size_t)co0*HW + p2) = make_float2(acc[mt][nt][0]+bv0, acc[mt][nt][1]+bv0);
            *(float2*)(dst + (size_t)co1*HW + p2) = make_float2(acc[mt][nt][2]+bv1, acc[mt][nt][3]+bv1);
        }
    }
}

// ---------------- BN stats ----------------
__inline__ __device__ float warpsum(float v) {
    #pragma unroll
    for (int o = 16; o; o >>= 1) v += __shfl_down_sync(0xFFFFFFFFu, v, o);
    return v;
}

__global__ __launch_bounds__(256) void bn_stats(const float* __restrict__ gam_off,
                                                const float* __restrict__ bet_off,
                                                const float* __restrict__ gam_mod,
                                                const float* __restrict__ bet_mod) {
    int ch = blockIdx.x;
    int tid = threadIdx.x;
    float s = 0.f, s2 = 0.f;
    for (int b = 0; b < BB; b++) {
        const float4* p = (const float4*)(g_t + ((size_t)(b*2*C + ch))*HW);
        for (int i = tid; i < HW/4; i += 256) {
            float4 v = p[i];
            s  += v.x + v.y + v.z + v.w;
            s2 += v.x*v.x + v.y*v.y + v.z*v.z + v.w*v.w;
        }
    }
    __shared__ float rs[8], rs2[8];
    int lane = tid & 31, wid = tid >> 5;
    s = warpsum(s); s2 = warpsum(s2);
    if (lane == 0) { rs[wid] = s; rs2[wid] = s2; }
    __syncthreads();
    if (wid == 0) {
        s  = (lane < 8) ? rs[lane]  : 0.f;
        s2 = (lane < 8) ? rs2[lane] : 0.f;
        s = warpsum(s); s2 = warpsum(s2);
        if (lane == 0) {
            float n = (float)(BB*HW);
            float m = s / n;
            float var = s2 / n - m*m;
            float ga = (ch < 64) ? __ldg(gam_off + ch) : __ldg(gam_mod + ch - 64);
            float be = (ch < 64) ? __ldg(bet_off + ch) : __ldg(bet_mod + ch - 64);
            float sc = ga * rsqrtf(var + EPSV);
            g_scale[ch] = sc;
            g_shift[ch] = be - m * sc;
        }
    }
}

// ---------------- BN apply + SiLU -> fp16 bits ----------------
__global__ __launch_bounds__(256) void bn_act_h() {
    int n4 = BB*2*C*HW/4;
    for (int i = blockIdx.x*blockDim.x + threadIdx.x; i < n4; i += gridDim.x*blockDim.x) {
        int c = (i >> 12) & 127;
        float sc = g_scale[c], sh = g_shift[c];
        float4 v = ((const float4*)g_t)[i];
        v.x = silu_f(v.x*sc + sh);
        v.y = silu_f(v.y*sc + sh);
        v.z = silu_f(v.z*sc + sh);
        v.w = silu_f(v.w*sc + sh);
        uint2 pk;
        pk.x = (uint32_t)h_bits(v.x) | ((uint32_t)h_bits(v.y) << 16);
        pk.y = (uint32_t)h_bits(v.z) | ((uint32_t)h_bits(v.w) << 16);
        ((uint2*)g_acth)[i] = pk;
    }
}

// ---------------- conv2: GEMM-ized, direct fp16 activation loads ------------
__global__ __launch_bounds__(256) void conv2_t(const float* __restrict__ off_b2,
                                               const float* __restrict__ mod_b2,
                                               float* __restrict__ offs,
                                               float* __restrict__ modu) {
    char* smem_c = smem_dyn;
    uint32_t smem_base = smem_u32(smem_c);
    int tid = threadIdx.x, wid = tid >> 5, lane = tid & 31;
    int blk = blockIdx.x;
    int b = blk >> 7, h = blk & 127;

    int wpx = wid * 16;
    float acc[2][2][4];
    #pragma unroll
    for (int mt = 0; mt < 2; mt++)
        #pragma unroll
        for (int nt = 0; nt < 2; nt++)
            #pragma unroll
            for (int q = 0; q < 4; q++) acc[mt][nt][q] = 0.f;

    int px = tid & 127, kh = tid >> 7;

    for (int ck = 0; ck < 18; ck++) {
        if (ck) __syncthreads();
        {
            const uint4* sa = (const uint4*)(g_w2 + (size_t)ck*32*SK);
            uint4* da = (uint4*)(smem_c + C2_OFF_A);
            for (int i = tid; i < 32*SK/8; i += 256) da[i] = sa[i];
        }
        {
            int ckm = ck % 9;
            int branch = ck / 9;
            const unsigned short* ab = g_acth + ((size_t)(b*COUT) + branch*64)*HW;
            int k0h = ckm*KC + kh*32;
            int c = k0h / 9, t = k0h - 9*c;
            #pragma unroll 8
            for (int kk2 = 0; kk2 < 32; kk2++) {
                int dy = t / 3, dxm = t - dy*3;
                int hh = h + dy - 1, ww = px + dxm - 1;
                unsigned short v = 0;
                if ((unsigned)hh < H && (unsigned)ww < W)
                    v = __ldg(ab + (size_t)c*HW + hh*W + ww);
                *(unsigned short*)(smem_c + C2_OFF_B + (kh*32 + kk2)*(SKB*2) + px*2) = v;
                if (++t == 9) { t = 0; c++; }
            }
        }
        __syncthreads();
        {
            uint32_t baseA = smem_base + C2_OFF_A;
            uint32_t baseB = smem_base + C2_OFF_B;
            #pragma unroll
            for (int ks = 0; ks < 4; ks++) {
                int k0 = ks * 16;
                uint32_t a[2][4];
                ldsm_x4(a[0], a_addr(baseA, 0, k0, lane));
                ldsm_x4(a[1], a_addr(baseA, 16, k0, lane));
                #pragma unroll
                for (int nt = 0; nt < 2; nt++) {
                    uint32_t bh[2];
                    ldsm_x2_t(bh, b_addr_t(baseB, k0, wpx + nt*8, lane));
                    mma_f16(acc[0][nt], a[0], bh);
                    mma_f16(acc[1][nt], a[1], bh);
                }
            }
        }
    }

    int g = lane >> 2, tg = lane & 3;
    #pragma unroll
    for (int mt = 0; mt < 2; mt++) {
        #pragma unroll
        for (int half = 0; half < 2; half++) {
            int row = mt*16 + half*8 + g;
            #pragma unroll
            for (int nt = 0; nt < 2; nt++) {
                int p2 = wpx + nt*8 + 2*tg;
                float v0 = acc[mt][nt][half*2 + 0];
                float v1 = acc[mt][nt][half*2 + 1];
                if (row < 18) {
                    float bv = __ldg(off_b2 + row);
                    *(float2*)(offs + ((size_t)(b*18 + row))*HW + h*W + p2) =
                        make_float2(v0 + bv, v1 + bv);
                } else if (row < 27) {
                    float bv = __ldg(mod_b2 + row - 18);
                    float s0 = __fdividef(1.f, 1.f + __expf(-(v0 + bv)));
                    float s1 = __fdividef(1.f, 1.f + __expf(-(v1 + bv)));
                    *(float2*)(modu + ((size_t)(b*9 + row - 18))*HW + h*W + p2) =
                        make_float2(s0, s1);
                }
            }
        }
    }
}

// ---------------- deform: mma GEMM, paired-gather producer ------------------
__global__ __launch_bounds__(256) void deform_t(const float* __restrict__ bias,
                                                float* __restrict__ out) {
    char* smem_c = smem_dyn;
    uint32_t smem_base = smem_u32(smem_c);
    int tid = threadIdx.x, wid = tid >> 5, lane = tid & 31;
    int blk = blockIdx.x;
    int b = blk >> 7, h = blk & 127;
    float4* sW4 = (float4*)(smem_c + OFF_TW4);
    int2*   sI2 = (int2*)(smem_c + OFF_TI2);

    // tap tables: per (tap, px): 4 corner weights + 2 pair-row indices
    for (int i = tid; i < 9*128; i += 256) {
        int tap = i >> 7, px = i & 127;
        size_t sp = (size_t)h*W + px;
        float offy = __ldg(g_offs + ((size_t)(b*18 + tap*2 + 1))*HW + sp);
        float offx = __ldg(g_offs + ((size_t)(b*18 + tap*2 + 0))*HW + sp);
        float m    = __ldg(g_modu + ((size_t)(b*9 + tap))*HW + sp);
        float sy = (float)h  + (float)(tap/3 - 1) + offy;
        float sx2 = (float)px + (float)(tap%3 - 1) + offx;
        float y0f = floorf(sy), x0f = floorf(sx2);
        int y0 = (int)y0f, x0 = (int)x0f;
        float wy1 = sy - y0f, wx1 = sx2 - x0f;
        float wy0 = 1.f - wy1, wx0 = 1.f - wx1;
        bool vx0 = (unsigned)x0 < W;
        bool vx1 = (unsigned)(x0+1) < W;
        bool vy0 = (unsigned)y0 < H;
        bool vy1 = (unsigned)(y0+1) < H;
        float4 w4;
        w4.x = (vy0 && vx0) ? wy0*wx0*m : 0.f;   // (y0,   x0)   -> lo of top pair
        w4.y = (vy0 && vx1) ? wy0*wx1*m : 0.f;   // (y0,   x0+1) -> hi of top pair
        w4.z = (vy1 && vx0) ? wy1*wx0*m : 0.f;   // (y0+1, x0)
        w4.w = (vy1 && vx1) ? wy1*wx1*m : 0.f;   // (y0+1, x0+1)
        int ip  = min(max(x0 + 1, 0), XPW - 1);
        int yc0 = min(max(y0,     0), H - 1);
        int yc1 = min(max(y0 + 1, 0), H - 1);
        sW4[tap*128 + px] = w4;
        sI2[tap*128 + px] = make_int2(yc0*XPW + ip, yc1*XPW + ip);
    }

    int wco = (wid >> 1) * 32;
    int wpx = (wid & 1) * 64;
    float acc[2][8][4];
    #pragma unroll
    for (int mt = 0; mt < 2; mt++)
        #pragma unroll
        for (int nt = 0; nt < 8; nt++)
            #pragma unroll
            for (int q = 0; q < 4; q++) acc[mt][nt][q] = 0.f;

    int px = tid & 127, kh = tid >> 7;
    __syncthreads();

    for (int ck = 0; ck < NCHUNK; ck++) {
        if (ck) __syncthreads();
        {
            const uint4* sa = (const uint4*)(g_w4 + (size_t)ck*COUT*SK);
            uint4* da = (uint4*)(smem_c + OFF_A);
            for (int i = tid; i < COUT*SK/8; i += 256) da[i] = sa[i];
        }
        int k0h = ck*KC + kh*32;
        #pragma unroll
        for (int t = 0; t < 9; t++) {
            float4 w4 = sW4[t*128 + px];
            int2   i2 = sI2[t*128 + px];
            int clo = (k0h - t + 8) / 9;
            int chi = (k0h + 31 - t) / 9;
            for (int c = clo; c <= chi; c++) {
                const uint32_t* xpc = g_xp + (size_t)((b*C + c)*H)*XPW;
                float2 f0 = up2(__ldg(xpc + i2.x));
                float2 f1 = up2(__ldg(xpc + i2.y));
                float v = w4.x * f0.x;
                v = fmaf(w4.y, f0.y, v);
                v = fmaf(w4.z, f1.x, v);
                v = fmaf(w4.w, f1.y, v);
                int kk = c*9 + t - ck*KC;
                *(unsigned short*)(smem_c + OFF_B + kk*(SKB*2) + px*2) = h_bits(v);
            }
        }
        __syncthreads();
        mma_chunk(smem_base, lane, wco, wpx, acc);
    }

    int g = lane >> 2, tg = lane & 3;
    float* dst = out + (size_t)b*COUT*HW + (size_t)h*W;
    #pragma unroll
    for (int mt = 0; mt < 2; mt++) {
        int co0 = wco + mt*16 + g;
        int co1 = co0 + 8;
        float bv0 = __ldg(bias + co0);
        float bv1 = __ldg(bias + co1);
        #pragma unroll
        for (int nt = 0; nt < 8; nt++) {
            int p2 = wpx + nt*8 + 2*tg;
            *(float2*)(dst + (size_t)co0*HW + p2) = make_float2(acc[mt][nt][0]+bv0, acc[mt][nt][1]+bv0);
            *(float2*)(dst + (size_t)co1*HW + p2) = make_float2(acc[mt][nt][2]+bv1, acc[mt][nt][3]+bv1);
        }
    }
}

// ---------------- launch ----------------
extern "C" void kernel_launch(void* const* d_in, const int* in_sizes, int n_in,
                              void* d_out, int out_size) {
    const float* x        = (const float*)d_in[0];
    const float* weight   = (const float*)d_in[1];
    const float* bias     = (const float*)d_in[2];
    const float* off_w1   = (const float*)d_in[3];
    const float* off_b1   = (const float*)d_in[4];
    const float* off_g    = (const float*)d_in[5];
    const float* off_be   = (const float*)d_in[6];
    const float* off_w2   = (const float*)d_in[7];
    const float* off_b2   = (const float*)d_in[8];
    const float* mod_w1   = (const float*)d_in[9];
    const float* mod_b1   = (const float*)d_in[10];
    const float* mod_g    = (const float*)d_in[11];
    const float* mod_be   = (const float*)d_in[12];
    const float* mod_w2   = (const float*)d_in[13];
    const float* mod_b2   = (const float*)d_in[14];
    float* out = (float*)d_out;

    cudaFuncSetAttribute(conv1_t, cudaFuncAttributeMaxDynamicSharedMemorySize, SMEM_C1);
    cudaFuncSetAttribute(conv2_t, cudaFuncAttributeMaxDynamicSharedMemorySize, SMEM_C2);
    cudaFuncSetAttribute(deform_t, cudaFuncAttributeMaxDynamicSharedMemorySize, SMEM_DEF);

    float *offs_ptr, *modu_ptr;
    cudaGetSymbolAddress((void**)&offs_ptr, g_offs);
    cudaGetSymbolAddress((void**)&modu_ptr, g_modu);

    prep_weights<<<(NCHUNK*COUT*KC + 255)/256, 256>>>(off_w1, mod_w1, weight);
    prep_w2<<<(18*32*KC + 255)/256, 256>>>(off_w2, mod_w2);
    prep_xpair<<<8192, 256>>>(x);
    conv1_t<<<1024, 256, SMEM_C1>>>(off_b1, mod_b1);
    bn_stats<<<128, 256>>>(off_g, off_be, mod_g, mod_be);
    bn_act_h<<<8192, 256>>>();
    conv2_t<<<1024, 256, SMEM_C2>>>(off_b2, mod_b2, offs_ptr, modu_ptr);
    deform_t<<<1024, 256, SMEM_DEF>>>(bias, out);
}

// round 15
// speedup vs baseline: 1.1411x; 1.0679x over previous
#include <cuda_runtime.h>
#include <cuda_fp16.h>
#include <math.h>
#include <stdint.h>

#define BB 8
#define C 64
#define COUT 128
#define H 128
#define W 128
#define HW (H*W)
#define KC 64
#define NCHUNK 9
#define SK 72              // A smem k-stride (fp16): 144B rows
#define SKB 136            // B smem px-stride (fp16): 272B rows
#define XPW 132            // xpair row width (u32 entries)
#define EPSV 1e-5f

// ---------------- smem layouts (byte offsets), double-buffered ----------------
// conv1 / deform: A0,A1 (18432 each), B0,B1 (17408 each)
#define OFF_A0  0
#define OFF_A1  18432
#define OFF_B0  36864
#define OFF_B1  54272
#define SMEM_C1 71680
#define OFF_TW4 71680                   // deform: float4 [9][128] = 18432
#define OFF_TI2 (71680 + 18432)         // deform: int2   [9][128] = 9216
#define SMEM_DEF (OFF_TI2 + 9216)       // 99328
// conv2: A0,A1 (4608 each), B0,B1 (17408 each)
#define C2_A0   0
#define C2_A1   4608
#define C2_B0   9216
#define C2_B1   26624
#define SMEM_C2 44032

// ---------------- device scratch (POD types only) ----------------
__device__ float g_t[BB*2*C*HW];
__device__ __align__(16) unsigned short g_acth[BB*COUT*HW];   // silu(bn) fp16 bits
__device__ __align__(16) uint32_t g_xp[BB*C*H*XPW];           // paired fp16 x
__device__ float g_offs[BB*18*HW];
__device__ float g_modu[BB*9*HW];
__device__ float g_scale[2*C];
__device__ float g_shift[2*C];
__device__ __align__(16) unsigned short g_w1[NCHUNK*COUT*SK];
__device__ __align__(16) unsigned short g_w4[NCHUNK*COUT*SK];
__device__ __align__(16) unsigned short g_w2[18*32*SK];

// ---------------- helpers ----------------
__device__ __forceinline__ uint32_t smem_u32(const void* p) {
    uint32_t a;
    asm("{ .reg .u64 t; cvta.to.shared.u64 t, %1; cvt.u32.u64 %0, t; }" : "=r"(a) : "l"(p));
    return a;
}
__device__ __forceinline__ unsigned short h_bits(float v) {
    __half h = __float2half_rn(v);
    return *reinterpret_cast<unsigned short*>(&h);
}
__device__ __forceinline__ void ldsm_x4(uint32_t a[4], uint32_t addr) {
    asm volatile("ldmatrix.sync.aligned.m8n8.x4.shared.b16 {%0,%1,%2,%3}, [%4];"
        : "=r"(a[0]), "=r"(a[1]), "=r"(a[2]), "=r"(a[3]) : "r"(addr));
}
__device__ __forceinline__ void ldsm_x2_t(uint32_t b[2], uint32_t addr) {
    asm volatile("ldmatrix.sync.aligned.m8n8.x2.trans.shared.b16 {%0,%1}, [%2];"
        : "=r"(b[0]), "=r"(b[1]) : "r"(addr));
}
__device__ __forceinline__ void mma_f16(float d[4], const uint32_t a[4], const uint32_t b[2]) {
    asm volatile("mma.sync.aligned.m16n8k16.row.col.f32.f16.f16.f32 "
        "{%0,%1,%2,%3}, {%4,%5,%6,%7}, {%8,%9}, {%0,%1,%2,%3};"
        : "+f"(d[0]), "+f"(d[1]), "+f"(d[2]), "+f"(d[3])
        : "r"(a[0]), "r"(a[1]), "r"(a[2]), "r"(a[3]), "r"(b[0]), "r"(b[1]));
}
__device__ __forceinline__ uint32_t a_addr(uint32_t base, int row0, int k0, int lane) {
    int q = lane >> 3;
    int row = row0 + (lane & 7) + (q & 1) * 8;
    int col = k0 + (q >> 1) * 8;
    return base + (uint32_t)(row * SK + col) * 2u;
}
__device__ __forceinline__ uint32_t b_addr_t(uint32_t base, int k0, int n0, int lane) {
    int row = k0 + (lane & 15);
    return base + (uint32_t)(row * SKB + n0) * 2u;
}
__device__ __forceinline__ float silu_f(float v) {
    return __fdividef(v, 1.f + __expf(-v));
}
__device__ __forceinline__ float2 up2(uint32_t u) {
    __half2 hv = *reinterpret_cast<__half2*>(&u);
    return __half22float2(hv);
}

// ---------------- weight prep ----------------
__global__ void prep_weights(const float* __restrict__ off_w1,
                             const float* __restrict__ mod_w1,
                             const float* __restrict__ wmain) {
    int i = blockIdx.x * 256 + threadIdx.x;
    if (i >= NCHUNK*COUT*KC) return;
    int ck = i / (COUT*KC);
    int r  = i - ck*(COUT*KC);
    int co = r >> 6;
    int j  = r & 63;
    int k = ck*KC + j;
    int c = k / 9, t = k - c*9;
    size_t soff = (size_t)(ck*COUT + co)*SK + j;
    float w1 = (co < 64) ? off_w1[(co*C + c)*9 + t] : mod_w1[((co-64)*C + c)*9 + t];
    g_w1[soff] = h_bits(w1);
    g_w4[soff] = h_bits(wmain[(co*C + c)*9 + t]);
}

__global__ void prep_w2(const float* __restrict__ off_w2,
                        const float* __restrict__ mod_w2) {
    int i = blockIdx.x * 256 + threadIdx.x;
    if (i >= 18*32*KC) return;
    int ck = i / (32*KC);
    int r  = i - ck*(32*KC);
    int row = r >> 6;
    int j   = r & 63;
    int kb = (ck % 9)*KC + j;
    int c = kb / 9, t = kb - c*9;
    int branch = ck / 9;
    float w = 0.f;
    if (branch == 0 && row < 18)       w = off_w2[(row*C + c)*9 + t];
    else if (branch == 1 && row >= 18 && row < 27) w = mod_w2[((row-18)*C + c)*9 + t];
    g_w2[(size_t)(ck*32 + row)*SK + j] = h_bits(w);
}

// ---------------- xpair prep ----------------
__global__ __launch_bounds__(256) void prep_xpair(const float* __restrict__ x) {
    int n = BB*C*H*XPW;
    for (int e = blockIdx.x*blockDim.x + threadIdx.x; e < n; e += gridDim.x*blockDim.x) {
        int row = e / XPW;
        int ip  = e - row*XPW;
        const float* xr = x + (size_t)row * W;
        float lo = (ip >= 1 && ip <= 128) ? __ldg(xr + ip - 1) : 0.f;
        float hi = (ip <= 127)            ? __ldg(xr + ip)     : 0.f;
        g_xp[e] = (uint32_t)h_bits(lo) | ((uint32_t)h_bits(hi) << 16);
    }
}

extern __shared__ char smem_dyn[];

// ---------------- shared GEMM consumer ----------------
__device__ __forceinline__ void mma_chunk(uint32_t baseA, uint32_t baseB, int lane,
                                          int wco, int wpx, float acc[2][8][4]) {
    #pragma unroll
    for (int ks = 0; ks < 4; ks++) {
        int k0 = ks * 16;
        uint32_t a[2][4];
        #pragma unroll
        for (int mt = 0; mt < 2; mt++)
            ldsm_x4(a[mt], a_addr(baseA, wco + mt*16, k0, lane));
        #pragma unroll
        for (int nt = 0; nt < 8; nt++) {
            uint32_t bh[2];
            ldsm_x2_t(bh, b_addr_t(baseB, k0, wpx + nt*8, lane));
            #pragma unroll
            for (int mt = 0; mt < 2; mt++)
                mma_f16(acc[mt][nt], a[mt], bh);
        }
    }
}

// ---------------- conv1 producer ----------------
__device__ __forceinline__ void c1_produce(char* smem_c, int tid, int b, int h, int ck,
                                           int aoff, int boff) {
    {
        const uint4* sa = (const uint4*)(g_w1 + (size_t)ck*COUT*SK);
        uint4* da = (uint4*)(smem_c + aoff);
        for (int i = tid; i < COUT*SK/8; i += 256) da[i] = sa[i];
    }
    int pxp = tid & 63, kq = tid >> 6;
    int kbase = kq*16;
    int kk = ck*KC + kbase;
    int c = kk / 9, t = kk - 9*c;
    #pragma unroll 8
    for (int j = 0; j < 16; j++) {
        int dy = t / 3, dxm = t - dy*3;
        int hh = h + dy - 1;
        uint32_t v = 0;
        if ((unsigned)hh < H)
            v = __ldg(g_xp + ((size_t)((b*C + c)*H + hh))*XPW + 2*pxp + dxm);
        *(uint32_t*)(smem_c + boff + (kbase + j)*(SKB*2) + pxp*4) = v;
        if (++t == 9) { t = 0; c++; }
    }
}

// ---------------- conv1: pipelined mma GEMM ----------------
__global__ void __launch_bounds__(256, 2) conv1_t(const float* __restrict__ b_off,
                                                  const float* __restrict__ b_mod) {
    char* smem_c = smem_dyn;
    uint32_t smem_base = smem_u32(smem_c);
    int tid = threadIdx.x, wid = tid >> 5, lane = tid & 31;
    int blk = blockIdx.x;
    int b = blk >> 7, h = blk & 127;

    int wco = (wid >> 1) * 32;
    int wpx = (wid & 1) * 64;
    float acc[2][8][4];
    #pragma unroll
    for (int mt = 0; mt < 2; mt++)
        #pragma unroll
        for (int nt = 0; nt < 8; nt++)
            #pragma unroll
            for (int q = 0; q < 4; q++) acc[mt][nt][q] = 0.f;

    c1_produce(smem_c, tid, b, h, 0, OFF_A0, OFF_B0);
    for (int ck = 0; ck < NCHUNK; ck++) {
        __syncthreads();
        int buf = ck & 1;
        mma_chunk(smem_base + (buf ? OFF_A1 : OFF_A0),
                  smem_base + (buf ? OFF_B1 : OFF_B0), lane, wco, wpx, acc);
        if (ck + 1 < NCHUNK)
            c1_produce(smem_c, tid, b, h, ck + 1,
                       (buf ? OFF_A0 : OFF_A1), (buf ? OFF_B0 : OFF_B1));
    }

    int g = lane >> 2, tg = lane & 3;
    float* dst = g_t + (size_t)b*COUT*HW + (size_t)h*W;
    #pragma unroll
    for (int mt = 0; mt < 2; mt++) {
        int co0 = wco + mt*16 + g;
        int co1 = co0 + 8;
        float bv0 = (co0 < 64) ? __ldg(b_off + co0) : __ldg(b_mod + co0 - 64);
        float bv1 = (co1 < 64) ? __ldg(b_off + co1) : __ldg(b_mod + co1 - 64);
        #pragma unroll
        for (int nt = 0; nt < 8; nt++) {
            int p2 = wpx + nt*8 + 2*tg;
            *(float2*)(dst + (size_t)co0*HW + p2) = make_float2(acc[mt][nt][0]+bv0, acc[mt][nt][1]+bv0);
            *(float2*)(dst + (size_t)co1*HW + p2) = make_float2(acc[mt][nt][2]+bv1, acc[mt][nt][3]+bv1);
        }
    }
}

// ---------------- BN stats ----------------
__inline__ __device__ float warpsum(float v) {
    #pragma unroll
    for (int o = 16; o; o >>= 1) v += __shfl_down_sync(0xFFFFFFFFu, v, o);
    return v;
}

__global__ __launch_bounds__(256) void bn_stats(const float* __restrict__ gam_off,
                                                const float* __restrict__ bet_off,
                                                const float* __restrict__ gam_mod,
                                                const float* __restrict__ bet_mod) {
    int ch = blockIdx.x;
    int tid = threadIdx.x;
    float s = 0.f, s2 = 0.f;
    for (int b = 0; b < BB; b++) {
        const float4* p = (const float4*)(g_t + ((size_t)(b*2*C + ch))*HW);
        for (int i = tid; i < HW/4; i += 256) {
            float4 v = p[i];
            s  += v.x + v.y + v.z + v.w;
            s2 += v.x*v.x + v.y*v.y + v.z*v.z + v.w*v.w;
        }
    }
    __shared__ float rs[8], rs2[8];
    int lane = tid & 31, wid = tid >> 5;
    s = warpsum(s); s2 = warpsum(s2);
    if (lane == 0) { rs[wid] = s; rs2[wid] = s2; }
    __syncthreads();
    if (wid == 0) {
        s  = (lane < 8) ? rs[lane]  : 0.f;
        s2 = (lane < 8) ? rs2[lane] : 0.f;
        s = warpsum(s); s2 = warpsum(s2);
        if (lane == 0) {
            float n = (float)(BB*HW);
            float m = s / n;
            float var = s2 / n - m*m;
            float ga = (ch < 64) ? __ldg(gam_off + ch) : __ldg(gam_mod + ch - 64);
            float be = (ch < 64) ? __ldg(bet_off + ch) : __ldg(bet_mod + ch - 64);
            float sc = ga * rsqrtf(var + EPSV);
            g_scale[ch] = sc;
            g_shift[ch] = be - m * sc;
        }
    }
}

// ---------------- BN apply + SiLU -> fp16 bits ----------------
__global__ __launch_bounds__(256) void bn_act_h() {
    int n4 = BB*2*C*HW/4;
    for (int i = blockIdx.x*blockDim.x + threadIdx.x; i < n4; i += gridDim.x*blockDim.x) {
        int c = (i >> 12) & 127;
        float sc = g_scale[c], sh = g_shift[c];
        float4 v = ((const float4*)g_t)[i];
        v.x = silu_f(v.x*sc + sh);
        v.y = silu_f(v.y*sc + sh);
        v.z = silu_f(v.z*sc + sh);
        v.w = silu_f(v.w*sc + sh);
        uint2 pk;
        pk.x = (uint32_t)h_bits(v.x) | ((uint32_t)h_bits(v.y) << 16);
        pk.y = (uint32_t)h_bits(v.z) | ((uint32_t)h_bits(v.w) << 16);
        ((uint2*)g_acth)[i] = pk;
    }
}

// ---------------- conv2 producer ----------------
__device__ __forceinline__ void c2_produce(char* smem_c, int tid, int b, int h, int ck,
                                           int aoff, int boff) {
    {
        const uint4* sa = (const uint4*)(g_w2 + (size_t)ck*32*SK);
        uint4* da = (uint4*)(smem_c + aoff);
        for (int i = tid; i < 32*SK/8; i += 256) da[i] = sa[i];
    }
    int px = tid & 127, kh = tid >> 7;
    int ckm = ck % 9;
    int branch = ck / 9;
    const unsigned short* ab = g_acth + ((size_t)(b*COUT) + branch*64)*HW;
    int k0h = ckm*KC + kh*32;
    int c = k0h / 9, t = k0h - 9*c;
    #pragma unroll 8
    for (int kk2 = 0; kk2 < 32; kk2++) {
        int dy = t / 3, dxm = t - dy*3;
        int hh = h + dy - 1, ww = px + dxm - 1;
        unsigned short v = 0;
        if ((unsigned)hh < H && (unsigned)ww < W)
            v = __ldg(ab + (size_t)c*HW + hh*W + ww);
        *(unsigned short*)(smem_c + boff + (kh*32 + kk2)*(SKB*2) + px*2) = v;
        if (++t == 9) { t = 0; c++; }
    }
}

// ---------------- conv2: pipelined GEMM (M=32, K=1152) ----------------
__global__ __launch_bounds__(256) void conv2_t(const float* __restrict__ off_b2,
                                               const float* __restrict__ mod_b2,
                                               float* __restrict__ offs,
                                               float* __restrict__ modu) {
    char* smem_c = smem_dyn;
    uint32_t smem_base = smem_u32(smem_c);
    int tid = threadIdx.x, wid = tid >> 5, lane = tid & 31;
    int blk = blockIdx.x;
    int b = blk >> 7, h = blk & 127;

    int wpx = wid * 16;
    float acc[2][2][4];
    #pragma unroll
    for (int mt = 0; mt < 2; mt++)
        #pragma unroll
        for (int nt = 0; nt < 2; nt++)
            #pragma unroll
            for (int q = 0; q < 4; q++) acc[mt][nt][q] = 0.f;

    c2_produce(smem_c, tid, b, h, 0, C2_A0, C2_B0);
    for (int ck = 0; ck < 18; ck++) {
        __syncthreads();
        int buf = ck & 1;
        uint32_t baseA = smem_base + (buf ? C2_A1 : C2_A0);
        uint32_t baseB = smem_base + (buf ? C2_B1 : C2_B0);
        #pragma unroll
        for (int ks = 0; ks < 4; ks++) {
            int k0 = ks * 16;
            uint32_t a[2][4];
            ldsm_x4(a[0], a_addr(baseA, 0, k0, lane));
            ldsm_x4(a[1], a_addr(baseA, 16, k0, lane));
            #pragma unroll
            for (int nt = 0; nt < 2; nt++) {
                uint32_t bh[2];
                ldsm_x2_t(bh, b_addr_t(baseB, k0, wpx + nt*8, lane));
                mma_f16(acc[0][nt], a[0], bh);
                mma_f16(acc[1][nt], a[1], bh);
            }
        }
        if (ck + 1 < 18)
            c2_produce(smem_c, tid, b, h, ck + 1,
                       (buf ? C2_A0 : C2_A1), (buf ? C2_B0 : C2_B1));
    }

    int g = lane >> 2, tg = lane & 3;
    #pragma unroll
    for (int mt = 0; mt < 2; mt++) {
        #pragma unroll
        for (int half = 0; half < 2; half++) {
            int row = mt*16 + half*8 + g;
            #pragma unroll
            for (int nt = 0; nt < 2; nt++) {
                int p2 = wpx + nt*8 + 2*tg;
                float v0 = acc[mt][nt][half*2 + 0];
                float v1 = acc[mt][nt][half*2 + 1];
                if (row < 18) {
                    float bv = __ldg(off_b2 + row);
                    *(float2*)(offs + ((size_t)(b*18 + row))*HW + h*W + p2) =
                        make_float2(v0 + bv, v1 + bv);
                } else if (row < 27) {
                    float bv = __ldg(mod_b2 + row - 18);
                    float s0 = __fdividef(1.f, 1.f + __expf(-(v0 + bv)));
                    float s1 = __fdividef(1.f, 1.f + __expf(-(v1 + bv)));
                    *(float2*)(modu + ((size_t)(b*9 + row - 18))*HW + h*W + p2) =
                        make_float2(s0, s1);
                }
            }
        }
    }
}

// ---------------- deform producer ----------------
__device__ __forceinline__ void df_produce(char* smem_c, int tid, int b, int ck,
                                           int aoff, int boff) {
    {
        const uint4* sa = (const uint4*)(g_w4 + (size_t)ck*COUT*SK);
        uint4* da = (uint4*)(smem_c + aoff);
        for (int i = tid; i < COUT*SK/8; i += 256) da[i] = sa[i];
    }
    int px = tid & 127, kh = tid >> 7;
    const float4* sW4 = (const float4*)(smem_c + OFF_TW4);
    const int2*   sI2 = (const int2*)(smem_c + OFF_TI2);
    int k0h = ck*KC + kh*32;
    #pragma unroll
    for (int t = 0; t < 9; t++) {
        float4 w4 = sW4[t*128 + px];
        int2   i2 = sI2[t*128 + px];
        int clo = (k0h - t + 8) / 9;
        int chi = (k0h + 31 - t) / 9;
        for (int c = clo; c <= chi; c++) {
            const uint32_t* xpc = g_xp + (size_t)((b*C + c)*H)*XPW;
            float2 f0 = up2(__ldg(xpc + i2.x));
            float2 f1 = up2(__ldg(xpc + i2.y));
            float v = w4.x * f0.x;
            v = fmaf(w4.y, f0.y, v);
            v = fmaf(w4.z, f1.x, v);
            v = fmaf(w4.w, f1.y, v);
            int kk = c*9 + t - ck*KC;
            *(unsigned short*)(smem_c + boff + kk*(SKB*2) + px*2) = h_bits(v);
        }
    }
}

// ---------------- deform: pipelined mma GEMM, paired gather -----------------
__global__ void __launch_bounds__(256, 2) deform_t(const float* __restrict__ bias,
                                                   float* __restrict__ out) {
    char* smem_c = smem_dyn;
    uint32_t smem_base = smem_u32(smem_c);
    int tid = threadIdx.x, wid = tid >> 5, lane = tid & 31;
    int blk = blockIdx.x;
    int b = blk >> 7, h = blk & 127;
    float4* sW4 = (float4*)(smem_c + OFF_TW4);
    int2*   sI2 = (int2*)(smem_c + OFF_TI2);

    // tap tables
    for (int i = tid; i < 9*128; i += 256) {
        int tap = i >> 7, px = i & 127;
        size_t sp = (size_t)h*W + px;
        float offy = __ldg(g_offs + ((size_t)(b*18 + tap*2 + 1))*HW + sp);
        float offx = __ldg(g_offs + ((size_t)(b*18 + tap*2 + 0))*HW + sp);
        float m    = __ldg(g_modu + ((size_t)(b*9 + tap))*HW + sp);
        float sy = (float)h  + (float)(tap/3 - 1) + offy;
        float sx2 = (float)px + (float)(tap%3 - 1) + offx;
        float y0f = floorf(sy), x0f = floorf(sx2);
        int y0 = (int)y0f, x0 = (int)x0f;
        float wy1 = sy - y0f, wx1 = sx2 - x0f;
        float wy0 = 1.f - wy1, wx0 = 1.f - wx1;
        bool vx0 = (unsigned)x0 < W;
        bool vx1 = (unsigned)(x0+1) < W;
        bool vy0 = (unsigned)y0 < H;
        bool vy1 = (unsigned)(y0+1) < H;
        float4 w4;
        w4.x = (vy0 && vx0) ? wy0*wx0*m : 0.f;
        w4.y = (vy0 && vx1) ? wy0*wx1*m : 0.f;
        w4.z = (vy1 && vx0) ? wy1*wx0*m : 0.f;
        w4.w = (vy1 && vx1) ? wy1*wx1*m : 0.f;
        int ip  = min(max(x0 + 1, 0), XPW - 1);
        int yc0 = min(max(y0,     0), H - 1);
        int yc1 = min(max(y0 + 1, 0), H - 1);
        sW4[tap*128 + px] = w4;
        sI2[tap*128 + px] = make_int2(yc0*XPW + ip, yc1*XPW + ip);
    }

    int wco = (wid >> 1) * 32;
    int wpx = (wid & 1) * 64;
    float acc[2][8][4];
    #pragma unroll
    for (int mt = 0; mt < 2; mt++)
        #pragma unroll
        for (int nt = 0; nt < 8; nt++)
            #pragma unroll
            for (int q = 0; q < 4; q++) acc[mt][nt][q] = 0.f;

    __syncthreads();                    // tap tables ready
    df_produce(smem_c, tid, b, 0, OFF_A0, OFF_B0);
    for (int ck = 0; ck < NCHUNK; ck++) {
        __syncthreads();
        int buf = ck & 1;
        mma_chunk(smem_base + (buf ? OFF_A1 : OFF_A0),
                  smem_base + (buf ? OFF_B1 : OFF_B0), lane, wco, wpx, acc);
        if (ck + 1 < NCHUNK)
            df_produce(smem_c, tid, b, ck + 1,
                       (buf ? OFF_A0 : OFF_A1), (buf ? OFF_B0 : OFF_B1));
    }

    int g = lane >> 2, tg = lane & 3;
    float* dst = out + (size_t)b*COUT*HW + (size_t)h*W;
    #pragma unroll
    for (int mt = 0; mt < 2; mt++) {
        int co0 = wco + mt*16 + g;
        int co1 = co0 + 8;
        float bv0 = __ldg(bias + co0);
        float bv1 = __ldg(bias + co1);
        #pragma unroll
        for (int nt = 0; nt < 8; nt++) {
            int p2 = wpx + nt*8 + 2*tg;
            *(float2*)(dst + (size_t)co0*HW + p2) = make_float2(acc[mt][nt][0]+bv0, acc[mt][nt][1]+bv0);
            *(float2*)(dst + (size_t)co1*HW + p2) = make_float2(acc[mt][nt][2]+bv1, acc[mt][nt][3]+bv1);
        }
    }
}

// ---------------- launch ----------------
extern "C" void kernel_launch(void* const* d_in, const int* in_sizes, int n_in,
                              void* d_out, int out_size) {
    const float* x        = (const float*)d_in[0];
    const float* weight   = (const float*)d_in[1];
    const float* bias     = (const float*)d_in[2];
    const float* off_w1   = (const float*)d_in[3];
    const float* off_b1   = (const float*)d_in[4];
    const float* off_g    = (const float*)d_in[5];
    const float* off_be   = (const float*)d_in[6];
    const float* off_w2   = (const float*)d_in[7];
    const float* off_b2   = (const float*)d_in[8];
    const float* mod_w1   = (const float*)d_in[9];
    const float* mod_b1   = (const float*)d_in[10];
    const float* mod_g    = (const float*)d_in[11];
    const float* mod_be   = (const float*)d_in[12];
    const float* mod_w2   = (const float*)d_in[13];
    const float* mod_b2   = (const float*)d_in[14];
    float* out = (float*)d_out;

    cudaFuncSetAttribute(conv1_t, cudaFuncAttributeMaxDynamicSharedMemorySize, SMEM_C1);
    cudaFuncSetAttribute(conv2_t, cudaFuncAttributeMaxDynamicSharedMemorySize, SMEM_C2);
    cudaFuncSetAttribute(deform_t, cudaFuncAttributeMaxDynamicSharedMemorySize, SMEM_DEF);

    float *offs_ptr, *modu_ptr;
    cudaGetSymbolAddress((void**)&offs_ptr, g_offs);
    cudaGetSymbolAddress((void**)&modu_ptr, g_modu);

    prep_weights<<<(NCHUNK*COUT*KC + 255)/256, 256>>>(off_w1, mod_w1, weight);
    prep_w2<<<(18*32*KC + 255)/256, 256>>>(off_w2, mod_w2);
    prep_xpair<<<8192, 256>>>(x);
    conv1_t<<<1024, 256, SMEM_C1>>>(off_b1, mod_b1);
    bn_stats<<<128, 256>>>(off_g, off_be, mod_g, mod_be);
    bn_act_h<<<8192, 256>>>();
    conv2_t<<<1024, 256, SMEM_C2>>>(off_b2, mod_b2, offs_ptr, modu_ptr);
    deform_t<<<1024, 256, SMEM_DEF>>>(bias, out);
}

// round 16
// speedup vs baseline: 1.2756x; 1.1178x over previous
#include <cuda_runtime.h>
#include <cuda_fp16.h>
#include <math.h>
#include <stdint.h>

#define BB 8
#define C 64
#define COUT 128
#define H 128
#define W 128
#define HW (H*W)
#define KC 64
#define NCHUNK 9
#define SK 72              // A smem k-stride (fp16): 144B rows
#define SKB 136            // B smem px-stride (fp16): 272B rows
#define XPW 132            // paired row width (u32 entries)
#define EPSV 1e-5f

// ---------------- smem layouts (byte offsets), double-buffered ----------------
#define OFF_A0  0
#define OFF_A1  18432
#define OFF_B0  36864
#define OFF_B1  54272
#define SMEM_C1 71680
#define OFF_TW4 71680                   // deform: float4 [9][128] = 18432
#define OFF_TI2 (71680 + 18432)         // deform: int2   [9][128] = 9216
#define SMEM_DEF (OFF_TI2 + 9216)       // 99328
// conv2: A0,A1 (4608 each), B0,B1 (17408 each)
#define C2_A0   0
#define C2_A1   4608
#define C2_B0   9216
#define C2_B1   26624
#define SMEM_C2 44032

// ---------------- device scratch (POD types only) ----------------
__device__ float g_t[BB*2*C*HW];
__device__ __align__(16) uint32_t g_ap[BB*COUT*H*XPW];        // paired silu(bn) fp16
__device__ __align__(16) uint32_t g_xp[BB*C*H*XPW];           // paired fp16 x
__device__ float g_offs[BB*18*HW];
__device__ float g_modu[BB*9*HW];
__device__ float g_ps[COUT*8];
__device__ float g_pq[COUT*8];
__device__ __align__(16) unsigned short g_w1[NCHUNK*COUT*SK];
__device__ __align__(16) unsigned short g_w4[NCHUNK*COUT*SK];
__device__ __align__(16) unsigned short g_w2[18*32*SK];

// ---------------- helpers ----------------
__device__ __forceinline__ uint32_t smem_u32(const void* p) {
    uint32_t a;
    asm("{ .reg .u64 t; cvta.to.shared.u64 t, %1; cvt.u32.u64 %0, t; }" : "=r"(a) : "l"(p));
    return a;
}
__device__ __forceinline__ unsigned short h_bits(float v) {
    __half h = __float2half_rn(v);
    return *reinterpret_cast<unsigned short*>(&h);
}
__device__ __forceinline__ void ldsm_x4(uint32_t a[4], uint32_t addr) {
    asm volatile("ldmatrix.sync.aligned.m8n8.x4.shared.b16 {%0,%1,%2,%3}, [%4];"
        : "=r"(a[0]), "=r"(a[1]), "=r"(a[2]), "=r"(a[3]) : "r"(addr));
}
__device__ __forceinline__ void ldsm_x2_t(uint32_t b[2], uint32_t addr) {
    asm volatile("ldmatrix.sync.aligned.m8n8.x2.trans.shared.b16 {%0,%1}, [%2];"
        : "=r"(b[0]), "=r"(b[1]) : "r"(addr));
}
__device__ __forceinline__ void mma_f16(float d[4], const uint32_t a[4], const uint32_t b[2]) {
    asm volatile("mma.sync.aligned.m16n8k16.row.col.f32.f16.f16.f32 "
        "{%0,%1,%2,%3}, {%4,%5,%6,%7}, {%8,%9}, {%0,%1,%2,%3};"
        : "+f"(d[0]), "+f"(d[1]), "+f"(d[2]), "+f"(d[3])
        : "r"(a[0]), "r"(a[1]), "r"(a[2]), "r"(a[3]), "r"(b[0]), "r"(b[1]));
}
__device__ __forceinline__ uint32_t a_addr(uint32_t base, int row0, int k0, int lane) {
    int q = lane >> 3;
    int row = row0 + (lane & 7) + (q & 1) * 8;
    int col = k0 + (q >> 1) * 8;
    return base + (uint32_t)(row * SK + col) * 2u;
}
__device__ __forceinline__ uint32_t b_addr_t(uint32_t base, int k0, int n0, int lane) {
    int row = k0 + (lane & 15);
    return base + (uint32_t)(row * SKB + n0) * 2u;
}
__device__ __forceinline__ float silu_f(float v) {
    return __fdividef(v, 1.f + __expf(-v));
}
__device__ __forceinline__ float2 up2(uint32_t u) {
    __half2 hv = *reinterpret_cast<__half2*>(&u);
    return __half22float2(hv);
}

// ---------------- weight prep ----------------
__global__ void prep_weights(const float* __restrict__ off_w1,
                             const float* __restrict__ mod_w1,
                             const float* __restrict__ wmain) {
    int i = blockIdx.x * 256 + threadIdx.x;
    if (i >= NCHUNK*COUT*KC) return;
    int ck = i / (COUT*KC);
    int r  = i - ck*(COUT*KC);
    int co = r >> 6;
    int j  = r & 63;
    int k = ck*KC + j;
    int c = k / 9, t = k - c*9;
    size_t soff = (size_t)(ck*COUT + co)*SK + j;
    float w1 = (co < 64) ? off_w1[(co*C + c)*9 + t] : mod_w1[((co-64)*C + c)*9 + t];
    g_w1[soff] = h_bits(w1);
    g_w4[soff] = h_bits(wmain[(co*C + c)*9 + t]);
}

__global__ void prep_w2(const float* __restrict__ off_w2,
                        const float* __restrict__ mod_w2) {
    int i = blockIdx.x * 256 + threadIdx.x;
    if (i >= 18*32*KC) return;
    int ck = i / (32*KC);
    int r  = i - ck*(32*KC);
    int row = r >> 6;
    int j   = r & 63;
    int kb = (ck % 9)*KC + j;
    int c = kb / 9, t = kb - c*9;
    int branch = ck / 9;
    float w = 0.f;
    if (branch == 0 && row < 18)       w = off_w2[(row*C + c)*9 + t];
    else if (branch == 1 && row >= 18 && row < 27) w = mod_w2[((row-18)*C + c)*9 + t];
    g_w2[(size_t)(ck*32 + row)*SK + j] = h_bits(w);
}

// ---------------- xpair prep ----------------
__global__ __launch_bounds__(256) void prep_xpair(const float* __restrict__ x) {
    int n = BB*C*H*XPW;
    for (int e = blockIdx.x*blockDim.x + threadIdx.x; e < n; e += gridDim.x*blockDim.x) {
        int row = e / XPW;
        int ip  = e - row*XPW;
        const float* xr = x + (size_t)row * W;
        float lo = (ip >= 1 && ip <= 128) ? __ldg(xr + ip - 1) : 0.f;
        float hi = (ip <= 127)            ? __ldg(xr + ip)     : 0.f;
        g_xp[e] = (uint32_t)h_bits(lo) | ((uint32_t)h_bits(hi) << 16);
    }
}

extern __shared__ char smem_dyn[];

// ---------------- shared GEMM consumer ----------------
__device__ __forceinline__ void mma_chunk(uint32_t baseA, uint32_t baseB, int lane,
                                          int wco, int wpx, float acc[2][8][4]) {
    #pragma unroll
    for (int ks = 0; ks < 4; ks++) {
        int k0 = ks * 16;
        uint32_t a[2][4];
        #pragma unroll
        for (int mt = 0; mt < 2; mt++)
            ldsm_x4(a[mt], a_addr(baseA, wco + mt*16, k0, lane));
        #pragma unroll
        for (int nt = 0; nt < 8; nt++) {
            uint32_t bh[2];
            ldsm_x2_t(bh, b_addr_t(baseB, k0, wpx + nt*8, lane));
            #pragma unroll
            for (int mt = 0; mt < 2; mt++)
                mma_f16(acc[mt][nt], a[mt], bh);
        }
    }
}

// ---------------- conv1 producer ----------------
__device__ __forceinline__ void c1_produce(char* smem_c, int tid, int b, int h, int ck,
                                           int aoff, int boff) {
    {
        const uint4* sa = (const uint4*)(g_w1 + (size_t)ck*COUT*SK);
        uint4* da = (uint4*)(smem_c + aoff);
        for (int i = tid; i < COUT*SK/8; i += 256) da[i] = sa[i];
    }
    int pxp = tid & 63, kq = tid >> 6;
    int kbase = kq*16;
    int kk = ck*KC + kbase;
    int c = kk / 9, t = kk - 9*c;
    #pragma unroll 8
    for (int j = 0; j < 16; j++) {
        int dy = t / 3, dxm = t - dy*3;
        int hh = h + dy - 1;
        uint32_t v = 0;
        if ((unsigned)hh < H)
            v = __ldg(g_xp + ((size_t)((b*C + c)*H + hh))*XPW + 2*pxp + dxm);
        *(uint32_t*)(smem_c + boff + (kbase + j)*(SKB*2) + pxp*4) = v;
        if (++t == 9) { t = 0; c++; }
    }
}

// ---------------- conv1: pipelined mma GEMM ----------------
__global__ void __launch_bounds__(256, 2) conv1_t(const float* __restrict__ b_off,
                                                  const float* __restrict__ b_mod) {
    char* smem_c = smem_dyn;
    uint32_t smem_base = smem_u32(smem_c);
    int tid = threadIdx.x, wid = tid >> 5, lane = tid & 31;
    int blk = blockIdx.x;
    int b = blk >> 7, h = blk & 127;

    int wco = (wid >> 1) * 32;
    int wpx = (wid & 1) * 64;
    float acc[2][8][4];
    #pragma unroll
    for (int mt = 0; mt < 2; mt++)
        #pragma unroll
        for (int nt = 0; nt < 8; nt++)
            #pragma unroll
            for (int q = 0; q < 4; q++) acc[mt][nt][q] = 0.f;

    c1_produce(smem_c, tid, b, h, 0, OFF_A0, OFF_B0);
    for (int ck = 0; ck < NCHUNK; ck++) {
        __syncthreads();
        int buf = ck & 1;
        mma_chunk(smem_base + (buf ? OFF_A1 : OFF_A0),
                  smem_base + (buf ? OFF_B1 : OFF_B0), lane, wco, wpx, acc);
        if (ck + 1 < NCHUNK)
            c1_produce(smem_c, tid, b, h, ck + 1,
                       (buf ? OFF_A0 : OFF_A1), (buf ? OFF_B0 : OFF_B1));
    }

    int g = lane >> 2, tg = lane & 3;
    float* dst = g_t + (size_t)b*COUT*HW + (size_t)h*W;
    #pragma unroll
    for (int mt = 0; mt < 2; mt++) {
        int co0 = wco + mt*16 + g;
        int co1 = co0 + 8;
        float bv0 = (co0 < 64) ? __ldg(b_off + co0) : __ldg(b_mod + co0 - 64);
        float bv1 = (co1 < 64) ? __ldg(b_off + co1) : __ldg(b_mod + co1 - 64);
        #pragma unroll
        for (int nt = 0; nt < 8; nt++) {
            int p2 = wpx + nt*8 + 2*tg;
            *(float2*)(dst + (size_t)co0*HW + p2) = make_float2(acc[mt][nt][0]+bv0, acc[mt][nt][1]+bv0);
            *(float2*)(dst + (size_t)co1*HW + p2) = make_float2(acc[mt][nt][2]+bv1, acc[mt][nt][3]+bv1);
        }
    }
}

// ---------------- BN stats: partials, grid (128, 8) ----------------
__inline__ __device__ float warpsum(float v) {
    #pragma unroll
    for (int o = 16; o; o >>= 1) v += __shfl_down_sync(0xFFFFFFFFu, v, o);
    return v;
}

__global__ __launch_bounds__(256) void bn_stats() {
    int ch = blockIdx.x;
    int b  = blockIdx.y;
    int tid = threadIdx.x;
    float s = 0.f, s2 = 0.f;
    const float4* p = (const float4*)(g_t + ((size_t)(b*COUT + ch))*HW);
    for (int i = tid; i < HW/4; i += 256) {
        float4 v = p[i];
        s  += v.x + v.y + v.z + v.w;
        s2 += v.x*v.x + v.y*v.y + v.z*v.z + v.w*v.w;
    }
    __shared__ float rs[8], rs2[8];
    int lane = tid & 31, wid = tid >> 5;
    s = warpsum(s); s2 = warpsum(s2);
    if (lane == 0) { rs[wid] = s; rs2[wid] = s2; }
    __syncthreads();
    if (wid == 0) {
        s  = (lane < 8) ? rs[lane]  : 0.f;
        s2 = (lane < 8) ? rs2[lane] : 0.f;
        s = warpsum(s); s2 = warpsum(s2);
        if (lane == 0) {
            g_ps[ch*8 + b] = s;
            g_pq[ch*8 + b] = s2;
        }
    }
}

// ---------------- BN finalize + SiLU -> paired fp16 bits --------------------
__global__ __launch_bounds__(256) void bn_act_p(const float* __restrict__ gam_off,
                                                const float* __restrict__ bet_off,
                                                const float* __restrict__ gam_mod,
                                                const float* __restrict__ bet_mod) {
    __shared__ float ssc[COUT], ssh[COUT];
    int tid = threadIdx.x;
    if (tid < COUT) {
        float s = 0.f, s2 = 0.f;
        #pragma unroll
        for (int b = 0; b < 8; b++) { s += g_ps[tid*8 + b]; s2 += g_pq[tid*8 + b]; }
        float n = (float)(BB*HW);
        float m = s / n;
        float var = s2 / n - m*m;
        float ga = (tid < 64) ? __ldg(gam_off + tid) : __ldg(gam_mod + tid - 64);
        float be = (tid < 64) ? __ldg(bet_off + tid) : __ldg(bet_mod + tid - 64);
        float sc = ga * rsqrtf(var + EPSV);
        ssc[tid] = sc;
        ssh[tid] = be - m * sc;
    }
    __syncthreads();

    int nq = BB*COUT*H*33;     // quads of paired entries (132/4 per row)
    for (int q = blockIdx.x*blockDim.x + tid; q < nq; q += gridDim.x*blockDim.x) {
        int row = q / 33;                 // (b*128 + cg)*128 + y
        int e0  = (q - row*33) * 4;
        int cg  = (row >> 7) & 127;
        float sc = ssc[cg], sh = ssh[cg];
        const float* tr = g_t + (size_t)row * W;
        float a[5];
        #pragma unroll
        for (int j = 0; j < 5; j++) {
            int vi = e0 - 1 + j;
            float raw = ((unsigned)vi < W) ? __ldg(tr + vi) : 0.f;
            a[j] = ((unsigned)vi < W) ? silu_f(raw*sc + sh) : 0.f;
        }
        uint4 pk;
        pk.x = (uint32_t)h_bits(a[0]) | ((uint32_t)h_bits(a[1]) << 16);
        pk.y = (uint32_t)h_bits(a[1]) | ((uint32_t)h_bits(a[2]) << 16);
        pk.z = (uint32_t)h_bits(a[2]) | ((uint32_t)h_bits(a[3]) << 16);
        pk.w = (uint32_t)h_bits(a[3]) | ((uint32_t)h_bits(a[4]) << 16);
        *(uint4*)(g_ap + (size_t)row*XPW + e0) = pk;
    }
}

// ---------------- conv2 producer (paired loads) ----------------
__device__ __forceinline__ void c2_produce(char* smem_c, int tid, int b, int h, int ck,
                                           int aoff, int boff) {
    {
        const uint4* sa = (const uint4*)(g_w2 + (size_t)ck*32*SK);
        uint4* da = (uint4*)(smem_c + aoff);
        for (int i = tid; i < 32*SK/8; i += 256) da[i] = sa[i];
    }
    int pxp = tid & 63, kq = tid >> 6;
    int kbase = kq*16;
    int ckm = ck % 9;
    int cb = (ck / 9) * 64;               // channel base for this branch
    int kk = ckm*KC + kbase;
    int c = kk / 9, t = kk - 9*c;
    #pragma unroll 8
    for (int j = 0; j < 16; j++) {
        int dy = t / 3, dxm = t - dy*3;
        int hh = h + dy - 1;
        uint32_t v = 0;
        if ((unsigned)hh < H)
            v = __ldg(g_ap + ((size_t)((b*COUT + cb + c)*H + hh))*XPW + 2*pxp + dxm);
        *(uint32_t*)(smem_c + boff + (kbase + j)*(SKB*2) + pxp*4) = v;
        if (++t == 9) { t = 0; c++; }
    }
}

// ---------------- conv2: pipelined GEMM (M=32, K=1152) ----------------
__global__ __launch_bounds__(256) void conv2_t(const float* __restrict__ off_b2,
                                               const float* __restrict__ mod_b2,
                                               float* __restrict__ offs,
                                               float* __restrict__ modu) {
    char* smem_c = smem_dyn;
    uint32_t smem_base = smem_u32(smem_c);
    int tid = threadIdx.x, wid = tid >> 5, lane = tid & 31;
    int blk = blockIdx.x;
    int b = blk >> 7, h = blk & 127;

    int wpx = wid * 16;
    float acc[2][2][4];
    #pragma unroll
    for (int mt = 0; mt < 2; mt++)
        #pragma unroll
        for (int nt = 0; nt < 2; nt++)
            #pragma unroll
            for (int q = 0; q < 4; q++) acc[mt][nt][q] = 0.f;

    c2_produce(smem_c, tid, b, h, 0, C2_A0, C2_B0);
    for (int ck = 0; ck < 18; ck++) {
        __syncthreads();
        int buf = ck & 1;
        uint32_t baseA = smem_base + (buf ? C2_A1 : C2_A0);
        uint32_t baseB = smem_base + (buf ? C2_B1 : C2_B0);
        #pragma unroll
        for (int ks = 0; ks < 4; ks++) {
            int k0 = ks * 16;
            uint32_t a[2][4];
            ldsm_x4(a[0], a_addr(baseA, 0, k0, lane));
            ldsm_x4(a[1], a_addr(baseA, 16, k0, lane));
            #pragma unroll
            for (int nt = 0; nt < 2; nt++) {
                uint32_t bh[2];
                ldsm_x2_t(bh, b_addr_t(baseB, k0, wpx + nt*8, lane));
                mma_f16(acc[0][nt], a[0], bh);
                mma_f16(acc[1][nt], a[1], bh);
            }
        }
        if (ck + 1 < 18)
            c2_produce(smem_c, tid, b, h, ck + 1,
                       (buf ? C2_A0 : C2_A1), (buf ? C2_B0 : C2_B1));
    }

    int g = lane >> 2, tg = lane & 3;
    #pragma unroll
    for (int mt = 0; mt < 2; mt++) {
        #pragma unroll
        for (int half = 0; half < 2; half++) {
            int row = mt*16 + half*8 + g;
            #pragma unroll
            for (int nt = 0; nt < 2; nt++) {
                int p2 = wpx + nt*8 + 2*tg;
                float v0 = acc[mt][nt][half*2 + 0];
                float v1 = acc[mt][nt][half*2 + 1];
                if (row < 18) {
                    float bv = __ldg(off_b2 + row);
                    *(float2*)(offs + ((size_t)(b*18 + row))*HW + h*W + p2) =
                        make_float2(v0 + bv, v1 + bv);
                } else if (row < 27) {
                    float bv = __ldg(mod_b2 + row - 18);
                    float s0 = __fdividef(1.f, 1.f + __expf(-(v0 + bv)));
                    float s1 = __fdividef(1.f, 1.f + __expf(-(v1 + bv)));
                    *(float2*)(modu + ((size_t)(b*9 + row - 18))*HW + h*W + p2) =
                        make_float2(s0, s1);
                }
            }
        }
    }
}

// ---------------- deform producer ----------------
__device__ __forceinline__ void df_produce(char* smem_c, int tid, int b, int ck,
                                           int aoff, int boff) {
    {
        const uint4* sa = (const uint4*)(g_w4 + (size_t)ck*COUT*SK);
        uint4* da = (uint4*)(smem_c + aoff);
        for (int i = tid; i < COUT*SK/8; i += 256) da[i] = sa[i];
    }
    int px = tid & 127, kh = tid >> 7;
    const float4* sW4 = (const float4*)(smem_c + OFF_TW4);
    const int2*   sI2 = (const int2*)(smem_c + OFF_TI2);
    int k0h = ck*KC + kh*32;
    #pragma unroll
    for (int t = 0; t < 9; t++) {
        float4 w4 = sW4[t*128 + px];
        int2   i2 = sI2[t*128 + px];
        int clo = (k0h - t + 8) / 9;
        int chi = (k0h + 31 - t) / 9;
        for (int c = clo; c <= chi; c++) {
            const uint32_t* xpc = g_xp + (size_t)((b*C + c)*H)*XPW;
            float2 f0 = up2(__ldg(xpc + i2.x));
            float2 f1 = up2(__ldg(xpc + i2.y));
            float v = w4.x * f0.x;
            v = fmaf(w4.y, f0.y, v);
            v = fmaf(w4.z, f1.x, v);
            v = fmaf(w4.w, f1.y, v);
            int kk = c*9 + t - ck*KC;
            *(unsigned short*)(smem_c + boff + kk*(SKB*2) + px*2) = h_bits(v);
        }
    }
}

// ---------------- deform: pipelined mma GEMM, paired gather -----------------
__global__ void __launch_bounds__(256, 2) deform_t(const float* __restrict__ bias,
                                                   float* __restrict__ out) {
    char* smem_c = smem_dyn;
    uint32_t smem_base = smem_u32(smem_c);
    int tid = threadIdx.x, wid = tid >> 5, lane = tid & 31;
    int blk = blockIdx.x;
    int b = blk >> 7, h = blk & 127;
    float4* sW4 = (float4*)(smem_c + OFF_TW4);
    int2*   sI2 = (int2*)(smem_c + OFF_TI2);

    for (int i = tid; i < 9*128; i += 256) {
        int tap = i >> 7, px = i & 127;
        size_t sp = (size_t)h*W + px;
        float offy = __ldg(g_offs + ((size_t)(b*18 + tap*2 + 1))*HW + sp);
        float offx = __ldg(g_offs + ((size_t)(b*18 + tap*2 + 0))*HW + sp);
        float m    = __ldg(g_modu + ((size_t)(b*9 + tap))*HW + sp);
        float sy = (float)h  + (float)(tap/3 - 1) + offy;
        float sx2 = (float)px + (float)(tap%3 - 1) + offx;
        float y0f = floorf(sy), x0f = floorf(sx2);
        int y0 = (int)y0f, x0 = (int)x0f;
        float wy1 = sy - y0f, wx1 = sx2 - x0f;
        float wy0 = 1.f - wy1, wx0 = 1.f - wx1;
        bool vx0 = (unsigned)x0 < W;
        bool vx1 = (unsigned)(x0+1) < W;
        bool vy0 = (unsigned)y0 < H;
        bool vy1 = (unsigned)(y0+1) < H;
        float4 w4;
        w4.x = (vy0 && vx0) ? wy0*wx0*m : 0.f;
        w4.y = (vy0 && vx1) ? wy0*wx1*m : 0.f;
        w4.z = (vy1 && vx0) ? wy1*wx0*m : 0.f;
        w4.w = (vy1 && vx1) ? wy1*wx1*m : 0.f;
        int ip  = min(max(x0 + 1, 0), XPW - 1);
        int yc0 = min(max(y0,     0), H - 1);
        int yc1 = min(max(y0 + 1, 0), H - 1);
        sW4[tap*128 + px] = w4;
        sI2[tap*128 + px] = make_int2(yc0*XPW + ip, yc1*XPW + ip);
    }

    int wco = (wid >> 1) * 32;
    int wpx = (wid & 1) * 64;
    float acc[2][8][4];
    #pragma unroll
    for (int mt = 0; mt < 2; mt++)
        #pragma unroll
        for (int nt = 0; nt < 8; nt++)
            #pragma unroll
            for (int q = 0; q < 4; q++) acc[mt][nt][q] = 0.f;

    __syncthreads();
    df_produce(smem_c, tid, b, 0, OFF_A0, OFF_B0);
    for (int ck = 0; ck < NCHUNK; ck++) {
        __syncthreads();
        int buf = ck & 1;
        mma_chunk(smem_base + (buf ? OFF_A1 : OFF_A0),
                  smem_base + (buf ? OFF_B1 : OFF_B0), lane, wco, wpx, acc);
        if (ck + 1 < NCHUNK)
            df_produce(smem_c, tid, b, ck + 1,
                       (buf ? OFF_A0 : OFF_A1), (buf ? OFF_B0 : OFF_B1));
    }

    int g = lane >> 2, tg = lane & 3;
    float* dst = out + (size_t)b*COUT*HW + (size_t)h*W;
    #pragma unroll
    for (int mt = 0; mt < 2; mt++) {
        int co0 = wco + mt*16 + g;
        int co1 = co0 + 8;
        float bv0 = __ldg(bias + co0);
        float bv1 = __ldg(bias + co1);
        #pragma unroll
        for (int nt = 0; nt < 8; nt++) {
            int p2 = wpx + nt*8 + 2*tg;
            *(float2*)(dst + (size_t)co0*HW + p2) = make_float2(acc[mt][nt][0]+bv0, acc[mt][nt][1]+bv0);
            *(float2*)(dst + (size_t)co1*HW + p2) = make_float2(acc[mt][nt][2]+bv1, acc[mt][nt][3]+bv1);
        }
    }
}

// ---------------- launch ----------------
extern "C" void kernel_launch(void* const* d_in, const int* in_sizes, int n_in,
                              void* d_out, int out_size) {
    const float* x        = (const float*)d_in[0];
    const float* weight   = (const float*)d_in[1];
    const float* bias     = (const float*)d_in[2];
    const float* off_w1   = (const float*)d_in[3];
    const float* off_b1   = (const float*)d_in[4];
    const float* off_g    = (const float*)d_in[5];
    const float* off_be   = (const float*)d_in[6];
    const float* off_w2   = (const float*)d_in[7];
    const float* off_b2   = (const float*)d_in[8];
    const float* mod_w1   = (const float*)d_in[9];
    const float* mod_b1   = (const float*)d_in[10];
    const float* mod_g    = (const float*)d_in[11];
    const float* mod_be   = (const float*)d_in[12];
    const float* mod_w2   = (const float*)d_in[13];
    const float* mod_b2   = (const float*)d_in[14];
    float* out = (float*)d_out;

    cudaFuncSetAttribute(conv1_t, cudaFuncAttributeMaxDynamicSharedMemorySize, SMEM_C1);
    cudaFuncSetAttribute(conv2_t, cudaFuncAttributeMaxDynamicSharedMemorySize, SMEM_C2);
    cudaFuncSetAttribute(deform_t, cudaFuncAttributeMaxDynamicSharedMemorySize, SMEM_DEF);

    float *offs_ptr, *modu_ptr;
    cudaGetSymbolAddress((void**)&offs_ptr, g_offs);
    cudaGetSymbolAddress((void**)&modu_ptr, g_modu);

    prep_weights<<<(NCHUNK*COUT*KC + 255)/256, 256>>>(off_w1, mod_w1, weight);
    prep_w2<<<(18*32*KC + 255)/256, 256>>>(off_w2, mod_w2);
    prep_xpair<<<8192, 256>>>(x);
    conv1_t<<<1024, 256, SMEM_C1>>>(off_b1, mod_b1);
    bn_stats<<<dim3(COUT, BB), 256>>>();
    bn_act_p<<<8192, 256>>>(off_g, off_be, mod_g, mod_be);
    conv2_t<<<1024, 256, SMEM_C2>>>(off_b2, mod_b2, offs_ptr, modu_ptr);
    deform_t<<<1024, 256, SMEM_DEF>>>(bias, out);
}